// round 9
// baseline (speedup 1.0000x reference)
#include <cuda_runtime.h>
#include <cuda_bf16.h>
#include <cuda_fp16.h>
#include <cstdint>
#include <math.h>

#define BB 128
#define TT 512
#define DD 128
#define HH 384
#define GG 1542
#define CONVW 10
#define HSS 64
#define NR (TT * BB)          /* 65536 rows */
#define NN 3840               /* K3 N = CONVW * HH */
#define K3K 384               /* K3 K (fp16 single pass) */
#define K1K 128               /* K1 K (fp16 single pass) */
#define K1NP 1664             /* K1 N padded */
#define K2NP 1600             /* K2 N padded */

// ---------------- static device scratch ----------------
__device__ float g_xk[(size_t)NR * GG];
__device__ float g_xout[BB * GG];
__device__ float g_h[(size_t)NR * HH];
__device__ float g_dist[NR];
__device__ float g_dis[NR * CONVW];
__device__ float g_A[(size_t)NR * NN];
__device__ __nv_bfloat16 g_hhi[(size_t)NR * HH];   // K2 A hi
__device__ __nv_bfloat16 g_hlo[(size_t)NR * HH];   // K2 A lo
__device__ __half g_hf[(size_t)NR * HH];           // K3 A (fp16)
__device__ __half g_wbh[(size_t)NN * K3K];         // K3 B (fp16)
__device__ __half g_xh[(size_t)NR * DD];           // K1 A (fp16)
__device__ __half g_wkh[(size_t)K1NP * K1K];       // K1 B (fp16)
__device__ __nv_bfloat16 g_wrhT[(size_t)K2NP * HH];   // K2 B hi
__device__ __nv_bfloat16 g_wrlT[(size_t)K2NP * HH];   // K2 B lo
__device__ volatile unsigned g_gflags[4][32];      // group-local barrier flags

// ---------------- helpers ----------------
__device__ __forceinline__ uint32_t smem_u32(const void* p) {
    uint32_t a;
    asm("{ .reg .u64 t; cvta.to.shared.u64 t, %1; cvt.u32.u64 %0, t; }" : "=r"(a) : "l"(p));
    return a;
}
__device__ __forceinline__ void cp16(uint32_t s, const void* g) {
    asm volatile("cp.async.cg.shared.global [%0], [%1], 16;" :: "r"(s), "l"(g));
}

#define K2_GRP 4
#define K2_PER 25

// group-local all-poll barrier: each block stores its flag, all blocks poll all flags.
__device__ __forceinline__ void k2bar(int grp, int nt, unsigned seq) {
    __threadfence();
    __syncthreads();
    if (threadIdx.x == 0) g_gflags[grp][nt] = seq;
    if (threadIdx.x < K2_PER) {
        while (g_gflags[grp][threadIdx.x] < seq) { __nanosleep(20); }
    }
    __syncthreads();
}

// ---------------- prep kernels ----------------
__global__ void __launch_bounds__(256) k_half_x(const float* __restrict__ x) {
    size_t idx = (size_t)blockIdx.x * 256 + threadIdx.x;   // float4 index
    if (idx >= (size_t)NR * DD / 4) return;
    size_t e = idx * 4;
    int d4 = (int)(e & 127);
    int r = (int)(e >> 7);
    int t = r >> 7, b = r & 127;
    float4 v = *reinterpret_cast<const float4*>(x + ((size_t)b * TT + t) * DD + d4);
    __half2* dst = reinterpret_cast<__half2*>(g_xh) + idx * 2;
    dst[0] = __floats2half2_rn(v.x, v.y);
    dst[1] = __floats2half2_rn(v.z, v.w);
}

__global__ void __launch_bounds__(256) k_prep_wk(const float* __restrict__ Wk) {
    size_t idx = (size_t)blockIdx.x * 256 + threadIdx.x;
    if (idx >= (size_t)K1NP * K1K) return;
    int i = (int)(idx % K1K);
    int n = (int)(idx / K1K);
    float w = (n < GG) ? Wk[(size_t)i * GG + n] : 0.f;
    g_wkh[idx] = __float2half(w);
}

__global__ void __launch_bounds__(256) k_prep_wr(const float* __restrict__ Wr) {
    size_t idx = (size_t)blockIdx.x * 256 + threadIdx.x;
    if (idx >= (size_t)K2NP * HH) return;
    int k = (int)(idx % HH);
    int n = (int)(idx / HH);
    float w = (n < GG) ? Wr[(size_t)k * GG + n] : 0.f;
    __nv_bfloat16 hi = __float2bfloat16(w);
    g_wrhT[idx] = hi;
    g_wrlT[idx] = __float2bfloat16(w - __bfloat162float(hi));
}

__global__ void __launch_bounds__(256) k_prep_w(const float* __restrict__ Wc) {
    size_t idx = (size_t)blockIdx.x * 256 + threadIdx.x;
    if (idx >= (size_t)NN * K3K) return;
    int i = (int)(idx % K3K);
    int n = (int)(idx / K3K);
    int k = n / HH, o = n - k * HH;
    g_wbh[idx] = __float2half(Wc[((size_t)o * HH + i) * CONVW + k]);
}

// ---------------- K1 GEMM: g_xk = [x,1]@Wk + bk via fp16 HMMA ----------------
#define ROWB 80
__global__ void __launch_bounds__(256, 2) k1_gemm(const float* __restrict__ Wk,
                                                  const float* __restrict__ bk) {
    __shared__ __align__(128) char sbuf[2][2 * 128 * ROWB];
    const int tid = threadIdx.x;
    const int wid = tid >> 5;
    const int lane = tid & 31;
    const int wm = wid >> 2, wn = wid & 3;
    const int n0 = blockIdx.x * 128;
    const size_t r0 = (size_t)blockIdx.y * 128;
    const int grow = tid >> 1, ghalf = tid & 1;

    uint32_t sA[2], sB[2];
#pragma unroll
    for (int s = 0; s < 2; ++s) {
        sA[s] = smem_u32(&sbuf[s][0]);
        sB[s] = smem_u32(&sbuf[s][128 * ROWB]);
    }
    const int q4 = lane >> 3;
    const uint32_t aoff = (uint32_t)(((q4 & 1) * 8 + (lane & 7)) * ROWB + (q4 >> 1) * 16);
    const uint32_t boff = (uint32_t)((lane & 7) * ROWB + ((lane >> 3) & 1) * 16);

    auto issue = [&](int ch) {
        const int kb = ch * 32;
        const int buf = ch & 1;
        const __half* ga = g_xh + (r0 + grow) * DD + kb + ghalf * 16;
        uint32_t da = sA[buf] + grow * ROWB + ghalf * 32;
        cp16(da, ga); cp16(da + 16, ga + 8);
        const __half* gb = g_wkh + (size_t)(n0 + grow) * K1K + kb + ghalf * 16;
        uint32_t db = sB[buf] + grow * ROWB + ghalf * 32;
        cp16(db, gb); cp16(db + 16, gb + 8);
        asm volatile("cp.async.commit_group;");
    };
    issue(0); issue(1);
    float c[4][4][4] = {};
    const int NCH1 = K1K / 32;   // 4
    for (int ch = 0; ch < NCH1; ++ch) {
        if (ch == NCH1 - 1) asm volatile("cp.async.wait_group 0;");
        else                asm volatile("cp.async.wait_group 1;");
        __syncthreads();
        const int buf = ch & 1;
        const uint32_t abase = sA[buf] + (wm * 64) * ROWB + aoff;
        const uint32_t bbase = sB[buf] + (wn * 32) * ROWB + boff;
#pragma unroll
        for (int s = 0; s < 2; ++s) {
            uint32_t a[4][4];
#pragma unroll
            for (int i = 0; i < 4; ++i) {
                asm volatile("ldmatrix.sync.aligned.m8n8.x4.shared.b16 {%0,%1,%2,%3}, [%4];"
                             : "=r"(a[i][0]), "=r"(a[i][1]), "=r"(a[i][2]), "=r"(a[i][3])
                             : "r"(abase + i * 16 * ROWB + s * 32));
            }
            uint32_t bf[4][2];
#pragma unroll
            for (int j = 0; j < 4; ++j) {
                asm volatile("ldmatrix.sync.aligned.m8n8.x2.shared.b16 {%0,%1}, [%2];"
                             : "=r"(bf[j][0]), "=r"(bf[j][1])
                             : "r"(bbase + j * 8 * ROWB + s * 32));
            }
#pragma unroll
            for (int i = 0; i < 4; ++i)
#pragma unroll
                for (int j = 0; j < 4; ++j)
                    asm volatile(
                        "mma.sync.aligned.m16n8k16.row.col.f32.f16.f16.f32 "
                        "{%0,%1,%2,%3}, {%4,%5,%6,%7}, {%8,%9}, {%0,%1,%2,%3};"
                        : "+f"(c[i][j][0]), "+f"(c[i][j][1]), "+f"(c[i][j][2]), "+f"(c[i][j][3])
                        : "r"(a[i][0]), "r"(a[i][1]), "r"(a[i][2]), "r"(a[i][3]),
                          "r"(bf[j][0]), "r"(bf[j][1]));
        }
        __syncthreads();
        if (ch + 2 < NCH1) issue(ch + 2);
    }
    const int gq = lane >> 2, t4 = lane & 3;
#pragma unroll
    for (int i = 0; i < 4; ++i) {
        size_t row = r0 + wm * 64 + i * 16 + gq;
#pragma unroll
        for (int j = 0; j < 4; ++j) {
            int g = n0 + wn * 32 + j * 8 + t4 * 2;
            if (g < GG) {
                float b0v = Wk[(size_t)DD * GG + g] + bk[g];
                float b1v = Wk[(size_t)DD * GG + g + 1] + bk[g + 1];
                g_xk[row * GG + g]           = c[i][j][0] + b0v;
                g_xk[row * GG + g + 1]       = c[i][j][1] + b1v;
                g_xk[(row + 8) * GG + g]     = c[i][j][2] + b0v;
                g_xk[(row + 8) * GG + g + 1] = c[i][j][3] + b1v;
            }
        }
    }
}

// ---------------- K2: persistent HMMA recurrent scan (4 groups x 25 blocks) ----------------
#define K2_PAD 784
#define K2_SM_WHI 0
#define K2_SM_WLO 50176
#define K2_SM_AHI 100352
#define K2_SM_ALO 125440
#define K2_SM_MST 150528
#define K2_SM_BIAS 152576
#define K2_SMEM 152832

__global__ void __launch_bounds__(256) k2_recurrent(const float* __restrict__ Wr,
                                                    const float* __restrict__ br) {
    extern __shared__ __align__(16) char s2[];
    const int tid = threadIdx.x;
    const int bid = blockIdx.x;
    const int grp = bid / K2_PER, nt = bid % K2_PER;
    const int b0 = grp * 32;
    const int n0 = nt * 64;

    // persistent B tiles (hi/lo) + bias
    for (int q = tid; q < 64 * 48; q += 256) {
        int row = q / 48, cc = q % 48;
        *reinterpret_cast<uint4*>(s2 + K2_SM_WHI + row * K2_PAD + cc * 16) =
            *reinterpret_cast<const uint4*>(g_wrhT + (size_t)(n0 + row) * HH + cc * 8);
        *reinterpret_cast<uint4*>(s2 + K2_SM_WLO + row * K2_PAD + cc * 16) =
            *reinterpret_cast<const uint4*>(g_wrlT + (size_t)(n0 + row) * HH + cc * 8);
    }
    float* s_bias = reinterpret_cast<float*>(s2 + K2_SM_BIAS);
    for (int n = tid; n < 64; n += 256) {
        int g = n0 + n;
        s_bias[n] = (g < GG) ? (Wr[(size_t)HH * GG + g] + br[g]) : 0.f;
    }
    float* s_mst = reinterpret_cast<float*>(s2 + K2_SM_MST);
    __syncthreads();

    unsigned seq = g_gflags[grp][nt];   // monotonic base (replay-safe)

    const int wid = tid >> 5, lane = tid & 31;
    const int wr = wid >> 2, wc = wid & 3;
    const int q4 = lane >> 3;
    const uint32_t fo = (uint32_t)(((q4 & 1) * 8 + (lane & 7)) * K2_PAD + (q4 >> 1) * 16);
    const uint32_t sbase = smem_u32(s2);
    const uint32_t a_hi = sbase + K2_SM_AHI + wr * 16 * K2_PAD + fo;
    const uint32_t a_lo = sbase + K2_SM_ALO + wr * 16 * K2_PAD + fo;
    const uint32_t b_hi = sbase + K2_SM_WHI + wc * 16 * K2_PAD + fo;
    const uint32_t b_lo = sbase + K2_SM_WLO + wc * 16 * K2_PAD + fo;
    const int gq = lane >> 2, t4 = lane & 3;

    // elementwise chunk ownership: 48 chunks of 256 over this group's 32x384 h elems
    const int ch0 = nt;                              // always valid
    const int ch1 = (nt + K2_PER < 48) ? nt + K2_PER : -1;
    float creg0 = 0.f, creg1 = 0.f;                  // cell state in registers

    for (int t = 0; t < TT; ++t) {
        float acc[2][4] = {};
        if (t > 0) {
            const size_t rb = (size_t)(t - 1) * BB + b0;
            for (int q = tid; q < 32 * 48; q += 256) {
                int row = q / 48, cc = q % 48;
                uint4 vh = __ldcg(reinterpret_cast<const uint4*>(
                    g_hhi + (rb + row) * HH + cc * 8));
                *reinterpret_cast<uint4*>(s2 + K2_SM_AHI + row * K2_PAD + cc * 16) = vh;
                uint4 vl = __ldcg(reinterpret_cast<const uint4*>(
                    g_hlo + (rb + row) * HH + cc * 8));
                *reinterpret_cast<uint4*>(s2 + K2_SM_ALO + row * K2_PAD + cc * 16) = vl;
            }
            __syncthreads();
#pragma unroll 1
            for (int pass = 0; pass < 3; ++pass) {
                const uint32_t ab = (pass == 2) ? a_lo : a_hi;
                const uint32_t bb = (pass == 1) ? b_lo : b_hi;
#pragma unroll
                for (int ki = 0; ki < 24; ++ki) {
                    uint32_t a[4], b[4];
                    asm volatile("ldmatrix.sync.aligned.m8n8.x4.shared.b16 {%0,%1,%2,%3}, [%4];"
                                 : "=r"(a[0]), "=r"(a[1]), "=r"(a[2]), "=r"(a[3])
                                 : "r"(ab + ki * 32));
                    asm volatile("ldmatrix.sync.aligned.m8n8.x4.shared.b16 {%0,%1,%2,%3}, [%4];"
                                 : "=r"(b[0]), "=r"(b[1]), "=r"(b[2]), "=r"(b[3])
                                 : "r"(bb + ki * 32));
                    asm volatile(
                        "mma.sync.aligned.m16n8k16.row.col.f32.bf16.bf16.f32 "
                        "{%0,%1,%2,%3}, {%4,%5,%6,%7}, {%8,%9}, {%0,%1,%2,%3};"
                        : "+f"(acc[0][0]), "+f"(acc[0][1]), "+f"(acc[0][2]), "+f"(acc[0][3])
                        : "r"(a[0]), "r"(a[1]), "r"(a[2]), "r"(a[3]),
                          "r"(b[0]), "r"(b[2]));
                    asm volatile(
                        "mma.sync.aligned.m16n8k16.row.col.f32.bf16.bf16.f32 "
                        "{%0,%1,%2,%3}, {%4,%5,%6,%7}, {%8,%9}, {%0,%1,%2,%3};"
                        : "+f"(acc[1][0]), "+f"(acc[1][1]), "+f"(acc[1][2]), "+f"(acc[1][3])
                        : "r"(a[0]), "r"(a[1]), "r"(a[2]), "r"(a[3]),
                          "r"(b[1]), "r"(b[3]));
                }
            }
        }
        // epilogue -> g_xout (rows b0..b0+31, cols n0..n0+63)
        {
            const float* xkrow = g_xk + (size_t)t * BB * GG;
            int b1 = b0 + wr * 16 + gq;
            int b2 = b1 + 8;
#pragma unroll
            for (int j = 0; j < 2; ++j) {
                int col = wc * 16 + j * 8 + t4 * 2;
                int g = n0 + col;
                if (g < GG) {
                    float bi0 = s_bias[col], bi1 = s_bias[col + 1];
                    g_xout[b1 * GG + g]     = acc[j][0] + bi0 + __ldcg(&xkrow[(size_t)b1 * GG + g]);
                    g_xout[b1 * GG + g + 1] = acc[j][1] + bi1 + __ldcg(&xkrow[(size_t)b1 * GG + g + 1]);
                    g_xout[b2 * GG + g]     = acc[j][2] + bi0 + __ldcg(&xkrow[(size_t)b2 * GG + g]);
                    g_xout[b2 * GG + g + 1] = acc[j][3] + bi1 + __ldcg(&xkrow[(size_t)b2 * GG + g + 1]);
                }
            }
        }
        ++seq; k2bar(grp, nt, seq);

        // masters for this group's 32 rows (every block computes; leader writes dist)
        if (tid < 32) {
            int b = b0 + tid;
            const float* row = g_xout + b * GG;
            float m0 = __ldcg(&row[0]), m1 = __ldcg(&row[1]), m2 = __ldcg(&row[2]);
            float v0 = __ldcg(&row[3]), v1 = __ldcg(&row[4]), v2 = __ldcg(&row[5]);
            float mx = fmaxf(m0, fmaxf(m1, m2));
            float e0 = expf(m0 - mx), e1 = expf(m1 - mx), e2 = expf(m2 - mx);
            float inv = 1.f / (e0 + e1 + e2);
            float f0 = e0 * inv, f1 = (e0 + e1) * inv;
            mx = fmaxf(v0, fmaxf(v1, v2));
            e0 = expf(v0 - mx); e1 = expf(v1 - mx); e2 = expf(v2 - mx);
            inv = 1.f / (e0 + e1 + e2);
            s_mst[tid * 4 + 0] = f0;
            s_mst[tid * 4 + 1] = f1;
            s_mst[tid * 4 + 2] = (e1 + e2) * inv;
            s_mst[tid * 4 + 3] = e2 * inv;
            if (nt == 0) g_dist[t * BB + b] = 1.f - (f0 + f1 + 1.f) * (1.f / 3.f);
        }
        __syncthreads();

        // elementwise for owned chunks (c in registers)
        {
            auto do_ew = [&](int ch, float& creg) {
                int e = ch * 256 + tid;          // 0..12287
                int r = e / 384, i = e - r * 384;
                int l = i >> 7, c127 = i & 127;
                int b = b0 + r;
                float fm = (l == 0) ? s_mst[r * 4] : ((l == 1) ? s_mst[r * 4 + 1] : 1.f);
                float im = (l == 0) ? 1.f : ((l == 1) ? s_mst[r * 4 + 2] : s_mst[r * 4 + 3]);
                float ov = fm * im;
                const float* row = g_xout + b * GG;
                float gf = __ldcg(&row[6 + l * 128 + c127]);
                float gi = __ldcg(&row[6 + (3 + l) * 128 + c127]);
                float go = __ldcg(&row[6 + (6 + l) * 128 + c127]);
                float gc = __ldcg(&row[6 + (9 + l) * 128 + c127]);
                float fg = 1.f / (1.f + expf(-gf));
                float ig = 1.f / (1.f + expf(-gi));
                float og = 1.f / (1.f + expf(-go));
                float ci = tanhf(gc);
                float cn = (ov * fg + fm - ov) * creg + (ov * ig + im - ov) * ci;
                float hn = og * tanhf(cn);
                creg = cn;
                size_t hx = (size_t)t * BB * HH + (size_t)b * HH + i;
                g_h[hx] = hn;
                __nv_bfloat16 hh = __float2bfloat16(hn);
                g_hhi[hx] = hh;
                g_hlo[hx] = __float2bfloat16(hn - __bfloat162float(hh));
                g_hf[hx] = __float2half(hn);
            };
            do_ew(ch0, creg0);
            if (ch1 >= 0) do_ew(ch1, creg1);
        }
        ++seq; k2bar(grp, nt, seq);
    }
}

// ---------------- K_dis ----------------
__global__ void k_dis() {
    int idx = blockIdx.x * 256 + threadIdx.x;
    if (idx >= NR) return;
    int t = idx >> 7, b = idx & 127;
    float c[CONVW];
    float cum = 0.f;
#pragma unroll
    for (int k = 0; k < CONVW; ++k) {
        int s = t - (CONVW - 1) + k;
        float d = (s >= 0) ? g_dist[s * BB + b] : 0.f;
        cum += d;
        c[k] = cum;
    }
    float mx = c[0];
#pragma unroll
    for (int k = 1; k < CONVW; ++k) mx = fmaxf(mx, c[k]);
    float sum = 0.f;
#pragma unroll
    for (int k = 0; k < CONVW; ++k) { c[k] = expf(c[k] - mx); sum += c[k]; }
    float inv = 1.f / sum;
#pragma unroll
    for (int k = 0; k < CONVW; ++k) g_dis[(size_t)idx * CONVW + k] = c[k] * inv;
}

// ---------------- K3 GEMM (fp16 single pass, K=384) ----------------
#define KSTEP 32
#define NCH3 (K3K / KSTEP)    /* 12 */
__global__ void __launch_bounds__(256, 2) k3_gemm() {
    __shared__ __align__(128) char sbuf[2][2 * 128 * ROWB];
    const int tid = threadIdx.x;
    const int wid = tid >> 5;
    const int lane = tid & 31;
    const int wm = wid >> 2, wn = wid & 3;
    const int n0 = blockIdx.x * 128;
    const size_t r0 = (size_t)blockIdx.y * 128;
    const int grow = tid >> 1, ghalf = tid & 1;
    uint32_t sA[2], sB[2];
#pragma unroll
    for (int s = 0; s < 2; ++s) {
        sA[s] = smem_u32(&sbuf[s][0]);
        sB[s] = smem_u32(&sbuf[s][128 * ROWB]);
    }
    const int q4 = lane >> 3;
    const uint32_t aoff = (uint32_t)(((q4 & 1) * 8 + (lane & 7)) * ROWB + (q4 >> 1) * 16);
    const uint32_t boff = (uint32_t)((lane & 7) * ROWB + ((lane >> 3) & 1) * 16);

    auto issue = [&](int ch) {
        const int kb = ch * KSTEP;
        const int buf = ch & 1;
        const __half* ga = g_hf + (r0 + grow) * HH + kb + ghalf * 16;
        uint32_t da = sA[buf] + grow * ROWB + ghalf * 32;
        cp16(da, ga); cp16(da + 16, ga + 8);
        const __half* gb = g_wbh + (size_t)(n0 + grow) * K3K + kb + ghalf * 16;
        uint32_t db = sB[buf] + grow * ROWB + ghalf * 32;
        cp16(db, gb); cp16(db + 16, gb + 8);
        asm volatile("cp.async.commit_group;");
    };
    issue(0); issue(1);
    float c[4][4][4] = {};
    for (int ch = 0; ch < NCH3; ++ch) {
        if (ch == NCH3 - 1) asm volatile("cp.async.wait_group 0;");
        else                asm volatile("cp.async.wait_group 1;");
        __syncthreads();
        const int buf = ch & 1;
        const uint32_t abase = sA[buf] + (wm * 64) * ROWB + aoff;
        const uint32_t bbase = sB[buf] + (wn * 32) * ROWB + boff;
#pragma unroll
        for (int s = 0; s < 2; ++s) {
            uint32_t a[4][4];
#pragma unroll
            for (int i = 0; i < 4; ++i) {
                asm volatile("ldmatrix.sync.aligned.m8n8.x4.shared.b16 {%0,%1,%2,%3}, [%4];"
                             : "=r"(a[i][0]), "=r"(a[i][1]), "=r"(a[i][2]), "=r"(a[i][3])
                             : "r"(abase + i * 16 * ROWB + s * 32));
            }
            uint32_t bfr[4][2];
#pragma unroll
            for (int j = 0; j < 4; ++j) {
                asm volatile("ldmatrix.sync.aligned.m8n8.x2.shared.b16 {%0,%1}, [%2];"
                             : "=r"(bfr[j][0]), "=r"(bfr[j][1])
                             : "r"(bbase + j * 8 * ROWB + s * 32));
            }
#pragma unroll
            for (int i = 0; i < 4; ++i)
#pragma unroll
                for (int j = 0; j < 4; ++j)
                    asm volatile(
                        "mma.sync.aligned.m16n8k16.row.col.f32.f16.f16.f32 "
                        "{%0,%1,%2,%3}, {%4,%5,%6,%7}, {%8,%9}, {%0,%1,%2,%3};"
                        : "+f"(c[i][j][0]), "+f"(c[i][j][1]), "+f"(c[i][j][2]), "+f"(c[i][j][3])
                        : "r"(a[i][0]), "r"(a[i][1]), "r"(a[i][2]), "r"(a[i][3]),
                          "r"(bfr[j][0]), "r"(bfr[j][1]));
        }
        __syncthreads();
        if (ch + 2 < NCH3) issue(ch + 2);
    }
    const int gq = lane >> 2, t4 = lane & 3;
#pragma unroll
    for (int i = 0; i < 4; ++i) {
        size_t row = r0 + wm * 64 + i * 16 + gq;
        float* dst0 = g_A + row * NN + n0 + wn * 32 + t4 * 2;
        float* dst1 = g_A + (row + 8) * NN + n0 + wn * 32 + t4 * 2;
#pragma unroll
        for (int j = 0; j < 4; ++j) {
            *reinterpret_cast<float2*>(dst0 + j * 8) = make_float2(c[i][j][0], c[i][j][1]);
            *reinterpret_cast<float2*>(dst1 + j * 8) = make_float2(c[i][j][2], c[i][j][3]);
        }
    }
}

// ---------------- K4: gather + theme MLP + final output ----------------
__global__ void __launch_bounds__(256) k4_out(const float* __restrict__ Ws,
                                              const float* __restrict__ bs,
                                              const float* __restrict__ Wrs,
                                              const float* __restrict__ brs,
                                              const float* __restrict__ bc,
                                              float* __restrict__ out) {
    __shared__ float s_mh[16][HH];
    __shared__ float s_q[16][HSS];
    __shared__ float s_dis2[16][10];
    const int tid = threadIdx.x;
    const int r0 = blockIdx.x * 16;
    const int t = r0 >> 7, b0 = r0 & 127;
    for (int lin = tid; lin < 160; lin += 256) {
        int rr = lin / 10, k = lin % 10;
        s_dis2[rr][k] = g_dis[(size_t)(r0 + rr) * CONVW + k];
    }
    __syncthreads();
    for (int idx = tid; idx < 16 * HH; idx += 256) {
        int rr = idx / HH, i = idx - rr * HH;
        float acc = 0.f;
#pragma unroll
        for (int k = 0; k < CONVW; ++k) {
            int s = t - (CONVW - 1) + k;
            if (s >= 0)
                acc += s_dis2[rr][k] * g_h[((size_t)s * BB + b0 + rr) * HH + i];
        }
        s_mh[rr][i] = acc * (1.f / CONVW);
    }
    __syncthreads();
    for (int idx = tid; idx < 16 * HSS; idx += 256) {
        int rr = idx >> 6, j = idx & 63;
        float acc = bs[j];
        for (int i = 0; i < HH; ++i) acc += s_mh[rr][i] * Ws[i * HSS + j];
        s_q[rr][j] = fmaxf(acc, 0.f);
    }
    __syncthreads();
    for (int idx = tid; idx < 16 * HH; idx += 256) {
        int rr = idx / HH, o = idx - rr * HH;
        float acc = brs[o];
#pragma unroll 8
        for (int j = 0; j < HSS; ++j) acc += s_q[rr][j] * Wrs[j * HH + o];
        float theme = 1.f / (1.f + expf(-acc));
        int b = b0 + rr;
        // inline gather: conv = bc + sum_k dis * A
        float conv = bc[o];
#pragma unroll
        for (int k = 0; k < CONVW; ++k) {
            int s = t - (CONVW - 1) + k;
            if (s >= 0)
                conv += s_dis2[rr][k] * g_A[((size_t)s * BB + b) * NN + (size_t)k * HH + o];
        }
        out[((size_t)b * TT + t) * HH + o] =
            theme * conv + g_h[((size_t)t * BB + b) * HH + o];
    }
}

// ---------------- entry ----------------
extern "C" void kernel_launch(void* const* d_in, const int* in_sizes, int n_in,
                              void* d_out, int out_size) {
    (void)in_sizes; (void)n_in; (void)out_size;
    const float* x   = (const float*)d_in[0];
    const float* Wk  = (const float*)d_in[2];
    const float* bk  = (const float*)d_in[3];
    const float* Wr  = (const float*)d_in[4];
    const float* br  = (const float*)d_in[5];
    const float* Ws  = (const float*)d_in[6];
    const float* bs  = (const float*)d_in[7];
    const float* Wrs = (const float*)d_in[8];
    const float* brs = (const float*)d_in[9];
    const float* Wc  = (const float*)d_in[10];
    const float* bc  = (const float*)d_in[11];
    float* out = (float*)d_out;

    cudaFuncSetAttribute(k2_recurrent, cudaFuncAttributeMaxDynamicSharedMemorySize, K2_SMEM);

    k_prep_w<<<(int)(((size_t)NN * K3K + 255) / 256), 256>>>(Wc);
    k_prep_wk<<<(int)(((size_t)K1NP * K1K + 255) / 256), 256>>>(Wk);
    k_prep_wr<<<(int)(((size_t)K2NP * HH + 255) / 256), 256>>>(Wr);
    k_half_x<<<(int)(((size_t)NR * DD / 4 + 255) / 256), 256>>>(x);
    k1_gemm<<<dim3(13, 512), 256>>>(Wk, bk);
    k2_recurrent<<<K2_GRP * K2_PER, 256, K2_SMEM>>>(Wr, br);
    k_dis<<<(NR + 255) / 256, 256>>>();
    k3_gemm<<<dim3(30, 512), 256>>>();
    k4_out<<<4096, 256>>>(Ws, bs, Wrs, brs, bc, out);
}

// round 10
// speedup vs baseline: 1.7205x; 1.7205x over previous
#include <cuda_runtime.h>
#include <cuda_bf16.h>
#include <cuda_fp16.h>
#include <cstdint>
#include <math.h>

#define BB 128
#define TT 512
#define DD 128
#define HH 384
#define GG 1542
#define CONVW 10
#define HSS 64
#define NR (TT * BB)          /* 65536 rows */
#define NN 3840               /* K3 N = CONVW * HH */
#define K3K 384               /* K3 K (fp16 single pass) */
#define K1K 128               /* K1 K (fp16 single pass) */
#define K1NP 1664             /* K1 N padded */
#define K2NP 1600             /* K2 N padded */

// ---------------- static device scratch ----------------
__device__ float g_xk[(size_t)NR * GG];
__device__ float g_xout[BB * GG];
__device__ float g_h[(size_t)NR * HH];
__device__ float g_c[BB * HH];
__device__ float g_dist[NR];
__device__ float g_dis[NR * CONVW];
__device__ float g_A[(size_t)NR * NN];
__device__ __nv_bfloat16 g_hhi[(size_t)NR * HH];   // K2 A hi
__device__ __nv_bfloat16 g_hlo[(size_t)NR * HH];   // K2 A lo
__device__ __half g_hf[(size_t)NR * HH];           // K3 A (fp16)
__device__ __half g_wbh[(size_t)NN * K3K];         // K3 B (fp16)
__device__ __half g_xh[(size_t)NR * DD];           // K1 A (fp16)
__device__ __half g_wkh[(size_t)K1NP * K1K];       // K1 B (fp16)
__device__ __nv_bfloat16 g_wrhT[(size_t)K2NP * HH];   // K2 B hi
__device__ __nv_bfloat16 g_wrlT[(size_t)K2NP * HH];   // K2 B lo
__device__ volatile unsigned g_flags[128];
__device__ volatile unsigned g_relsd;

// ---------------- helpers ----------------
__device__ __forceinline__ uint32_t smem_u32(const void* p) {
    uint32_t a;
    asm("{ .reg .u64 t; cvta.to.shared.u64 t, %1; cvt.u32.u64 %0, t; }" : "=r"(a) : "l"(p));
    return a;
}
__device__ __forceinline__ void cp16(uint32_t s, const void* g) {
    asm volatile("cp.async.cg.shared.global [%0], [%1], 16;" :: "r"(s), "l"(g));
}

#define K2_NB 100

// flag-based grid barrier (replay-safe via monotonic release counter)
__device__ __forceinline__ void gbar(unsigned seq) {
    __threadfence();
    __syncthreads();
    if (blockIdx.x == 0) {
        if (threadIdx.x > 0 && threadIdx.x < K2_NB) {
            while (g_flags[threadIdx.x] < seq) { __nanosleep(40); }
        }
        __syncthreads();
        if (threadIdx.x == 0) g_relsd = seq;
        __syncthreads();
    } else {
        if (threadIdx.x == 0) {
            g_flags[blockIdx.x] = seq;
            while (g_relsd < seq) { __nanosleep(40); }
            __threadfence();
        }
        __syncthreads();
    }
}

// ---------------- prep kernels ----------------
__global__ void __launch_bounds__(256) k_half_x(const float* __restrict__ x) {
    size_t idx = (size_t)blockIdx.x * 256 + threadIdx.x;   // float4 index
    if (idx >= (size_t)NR * DD / 4) return;
    size_t e = idx * 4;
    int d4 = (int)(e & 127);
    int r = (int)(e >> 7);
    int t = r >> 7, b = r & 127;
    float4 v = *reinterpret_cast<const float4*>(x + ((size_t)b * TT + t) * DD + d4);
    __half2* dst = reinterpret_cast<__half2*>(g_xh) + idx * 2;
    dst[0] = __floats2half2_rn(v.x, v.y);
    dst[1] = __floats2half2_rn(v.z, v.w);
}

__global__ void __launch_bounds__(256) k_prep_wk(const float* __restrict__ Wk) {
    size_t idx = (size_t)blockIdx.x * 256 + threadIdx.x;
    if (idx >= (size_t)K1NP * K1K) return;
    int i = (int)(idx % K1K);
    int n = (int)(idx / K1K);
    float w = (n < GG) ? Wk[(size_t)i * GG + n] : 0.f;
    g_wkh[idx] = __float2half(w);
}

__global__ void __launch_bounds__(256) k_prep_wr(const float* __restrict__ Wr) {
    size_t idx = (size_t)blockIdx.x * 256 + threadIdx.x;
    if (idx >= (size_t)K2NP * HH) return;
    int k = (int)(idx % HH);
    int n = (int)(idx / HH);
    float w = (n < GG) ? Wr[(size_t)k * GG + n] : 0.f;
    __nv_bfloat16 hi = __float2bfloat16(w);
    g_wrhT[idx] = hi;
    g_wrlT[idx] = __float2bfloat16(w - __bfloat162float(hi));
}

__global__ void __launch_bounds__(256) k_prep_w(const float* __restrict__ Wc) {
    size_t idx = (size_t)blockIdx.x * 256 + threadIdx.x;
    if (idx >= (size_t)NN * K3K) return;
    int i = (int)(idx % K3K);
    int n = (int)(idx / K3K);
    int k = n / HH, o = n - k * HH;
    g_wbh[idx] = __float2half(Wc[((size_t)o * HH + i) * CONVW + k]);
}

// ---------------- K1 GEMM: g_xk = [x,1]@Wk + bk via fp16 HMMA ----------------
#define ROWB 80
__global__ void __launch_bounds__(256, 2) k1_gemm(const float* __restrict__ Wk,
                                                  const float* __restrict__ bk) {
    __shared__ __align__(128) char sbuf[2][2 * 128 * ROWB];
    const int tid = threadIdx.x;
    const int wid = tid >> 5;
    const int lane = tid & 31;
    const int wm = wid >> 2, wn = wid & 3;
    const int n0 = blockIdx.x * 128;
    const size_t r0 = (size_t)blockIdx.y * 128;
    const int grow = tid >> 1, ghalf = tid & 1;

    uint32_t sA[2], sB[2];
#pragma unroll
    for (int s = 0; s < 2; ++s) {
        sA[s] = smem_u32(&sbuf[s][0]);
        sB[s] = smem_u32(&sbuf[s][128 * ROWB]);
    }
    const int q4 = lane >> 3;
    const uint32_t aoff = (uint32_t)(((q4 & 1) * 8 + (lane & 7)) * ROWB + (q4 >> 1) * 16);
    const uint32_t boff = (uint32_t)((lane & 7) * ROWB + ((lane >> 3) & 1) * 16);

    auto issue = [&](int ch) {
        const int kb = ch * 32;
        const int buf = ch & 1;
        const __half* ga = g_xh + (r0 + grow) * DD + kb + ghalf * 16;
        uint32_t da = sA[buf] + grow * ROWB + ghalf * 32;
        cp16(da, ga); cp16(da + 16, ga + 8);
        const __half* gb = g_wkh + (size_t)(n0 + grow) * K1K + kb + ghalf * 16;
        uint32_t db = sB[buf] + grow * ROWB + ghalf * 32;
        cp16(db, gb); cp16(db + 16, gb + 8);
        asm volatile("cp.async.commit_group;");
    };
    issue(0); issue(1);
    float c[4][4][4] = {};
    const int NCH1 = K1K / 32;   // 4
    for (int ch = 0; ch < NCH1; ++ch) {
        if (ch == NCH1 - 1) asm volatile("cp.async.wait_group 0;");
        else                asm volatile("cp.async.wait_group 1;");
        __syncthreads();
        const int buf = ch & 1;
        const uint32_t abase = sA[buf] + (wm * 64) * ROWB + aoff;
        const uint32_t bbase = sB[buf] + (wn * 32) * ROWB + boff;
#pragma unroll
        for (int s = 0; s < 2; ++s) {
            uint32_t a[4][4];
#pragma unroll
            for (int i = 0; i < 4; ++i) {
                asm volatile("ldmatrix.sync.aligned.m8n8.x4.shared.b16 {%0,%1,%2,%3}, [%4];"
                             : "=r"(a[i][0]), "=r"(a[i][1]), "=r"(a[i][2]), "=r"(a[i][3])
                             : "r"(abase + i * 16 * ROWB + s * 32));
            }
            uint32_t bf[4][2];
#pragma unroll
            for (int j = 0; j < 4; ++j) {
                asm volatile("ldmatrix.sync.aligned.m8n8.x2.shared.b16 {%0,%1}, [%2];"
                             : "=r"(bf[j][0]), "=r"(bf[j][1])
                             : "r"(bbase + j * 8 * ROWB + s * 32));
            }
#pragma unroll
            for (int i = 0; i < 4; ++i)
#pragma unroll
                for (int j = 0; j < 4; ++j)
                    asm volatile(
                        "mma.sync.aligned.m16n8k16.row.col.f32.f16.f16.f32 "
                        "{%0,%1,%2,%3}, {%4,%5,%6,%7}, {%8,%9}, {%0,%1,%2,%3};"
                        : "+f"(c[i][j][0]), "+f"(c[i][j][1]), "+f"(c[i][j][2]), "+f"(c[i][j][3])
                        : "r"(a[i][0]), "r"(a[i][1]), "r"(a[i][2]), "r"(a[i][3]),
                          "r"(bf[j][0]), "r"(bf[j][1]));
        }
        __syncthreads();
        if (ch + 2 < NCH1) issue(ch + 2);
    }
    const int gq = lane >> 2, t4 = lane & 3;
#pragma unroll
    for (int i = 0; i < 4; ++i) {
        size_t row = r0 + wm * 64 + i * 16 + gq;
#pragma unroll
        for (int j = 0; j < 4; ++j) {
            int g = n0 + wn * 32 + j * 8 + t4 * 2;
            if (g < GG) {
                float b0v = Wk[(size_t)DD * GG + g] + bk[g];
                float b1v = Wk[(size_t)DD * GG + g + 1] + bk[g + 1];
                g_xk[row * GG + g]           = c[i][j][0] + b0v;
                g_xk[row * GG + g + 1]       = c[i][j][1] + b1v;
                g_xk[(row + 8) * GG + g]     = c[i][j][2] + b0v;
                g_xk[(row + 8) * GG + g + 1] = c[i][j][3] + b1v;
            }
        }
    }
}

// ---------------- K2: persistent HMMA recurrent scan (R7 proven version) ----------------
#define K2_PAD 784
#define K2_SM_WHI 0
#define K2_SM_WLO 50176
#define K2_SM_AHI 100352
#define K2_SM_ALO 125440
#define K2_SM_MST 150528
#define K2_SM_BIAS 152576
#define K2_SMEM 152832

__global__ void __launch_bounds__(256) k2_recurrent(const float* __restrict__ Wr,
                                                    const float* __restrict__ br) {
    extern __shared__ __align__(16) char s2[];
    const int tid = threadIdx.x;
    const int bid = blockIdx.x;
    const int mt = bid / 25, nt = bid % 25;
    const int b0 = mt * 16;
    const int n0 = nt * 64;
    const unsigned base = g_relsd;

    // NOTE: 100 blocks = 4 m-tiles? No: R7 used bid/17 layout with 136; here
    // proven R7 config: 100 blocks = 4 m-tiles (32 rows) x 25 n-tiles (64 cols).
    const int mt4 = bid / 25;
    const int bm0 = mt4 * 32;

    // persistent B load (hi/lo) + bias: 64 rows x 48 16B-chunks (= HH bf16)
    for (int q = tid; q < 64 * 48; q += 256) {
        int row = q / 48, cc = q % 48;
        *reinterpret_cast<uint4*>(s2 + K2_SM_WHI + row * K2_PAD + cc * 16) =
            *reinterpret_cast<const uint4*>(g_wrhT + (size_t)(n0 + row) * HH + cc * 8);
        *reinterpret_cast<uint4*>(s2 + K2_SM_WLO + row * K2_PAD + cc * 16) =
            *reinterpret_cast<const uint4*>(g_wrlT + (size_t)(n0 + row) * HH + cc * 8);
    }
    float* s_bias = reinterpret_cast<float*>(s2 + K2_SM_BIAS);
    for (int n = tid; n < 64; n += 256) {
        int g = n0 + n;
        s_bias[n] = (g < GG) ? (Wr[(size_t)HH * GG + g] + br[g]) : 0.f;
    }
    float* s_mst = reinterpret_cast<float*>(s2 + K2_SM_MST);
    for (int i = bid * 256 + tid; i < BB * HH; i += K2_NB * 256) g_c[i] = 0.f;
    unsigned seq = base + 1;
    gbar(seq);

    const int wid = tid >> 5, lane = tid & 31;
    const int wr = wid >> 2, wc = wid & 3;
    const int q4 = lane >> 3;
    const uint32_t fo = (uint32_t)(((q4 & 1) * 8 + (lane & 7)) * K2_PAD + (q4 >> 1) * 16);
    const uint32_t sbase = smem_u32(s2);
    const uint32_t a_hi = sbase + K2_SM_AHI + wr * 16 * K2_PAD + fo;
    const uint32_t a_lo = sbase + K2_SM_ALO + wr * 16 * K2_PAD + fo;
    const uint32_t b_hi = sbase + K2_SM_WHI + wc * 16 * K2_PAD + fo;
    const uint32_t b_lo = sbase + K2_SM_WLO + wc * 16 * K2_PAD + fo;
    const int gq = lane >> 2, t4 = lane & 3;

    for (int t = 0; t < TT; ++t) {
        float acc[2][4] = {};
        if (t > 0) {
            const size_t rb = (size_t)(t - 1) * BB + bm0;
            // A tiles: 32 rows x 48 16B-chunks (hi and lo)
            for (int q = tid; q < 32 * 48; q += 256) {
                int row = q / 48, cc = q % 48;
                uint4 vh = __ldcg(reinterpret_cast<const uint4*>(
                    g_hhi + (rb + row) * HH + cc * 8));
                *reinterpret_cast<uint4*>(s2 + K2_SM_AHI + row * K2_PAD + cc * 16) = vh;
                uint4 vl = __ldcg(reinterpret_cast<const uint4*>(
                    g_hlo + (rb + row) * HH + cc * 8));
                *reinterpret_cast<uint4*>(s2 + K2_SM_ALO + row * K2_PAD + cc * 16) = vl;
            }
            __syncthreads();
#pragma unroll 1
            for (int pass = 0; pass < 3; ++pass) {
                const uint32_t ab = (pass == 2) ? a_lo : a_hi;
                const uint32_t bb = (pass == 1) ? b_lo : b_hi;
#pragma unroll
                for (int ki = 0; ki < 24; ++ki) {
                    uint32_t a[4], b[4];
                    asm volatile("ldmatrix.sync.aligned.m8n8.x4.shared.b16 {%0,%1,%2,%3}, [%4];"
                                 : "=r"(a[0]), "=r"(a[1]), "=r"(a[2]), "=r"(a[3])
                                 : "r"(ab + ki * 32));
                    asm volatile("ldmatrix.sync.aligned.m8n8.x4.shared.b16 {%0,%1,%2,%3}, [%4];"
                                 : "=r"(b[0]), "=r"(b[1]), "=r"(b[2]), "=r"(b[3])
                                 : "r"(bb + ki * 32));
                    asm volatile(
                        "mma.sync.aligned.m16n8k16.row.col.f32.bf16.bf16.f32 "
                        "{%0,%1,%2,%3}, {%4,%5,%6,%7}, {%8,%9}, {%0,%1,%2,%3};"
                        : "+f"(acc[0][0]), "+f"(acc[0][1]), "+f"(acc[0][2]), "+f"(acc[0][3])
                        : "r"(a[0]), "r"(a[1]), "r"(a[2]), "r"(a[3]),
                          "r"(b[0]), "r"(b[2]));
                    asm volatile(
                        "mma.sync.aligned.m16n8k16.row.col.f32.bf16.bf16.f32 "
                        "{%0,%1,%2,%3}, {%4,%5,%6,%7}, {%8,%9}, {%0,%1,%2,%3};"
                        : "+f"(acc[1][0]), "+f"(acc[1][1]), "+f"(acc[1][2]), "+f"(acc[1][3])
                        : "r"(a[0]), "r"(a[1]), "r"(a[2]), "r"(a[3]),
                          "r"(b[1]), "r"(b[3]));
                }
            }
        }
        // epilogue -> g_xout
        {
            const float* xkrow = g_xk + (size_t)t * BB * GG;
            int b1 = bm0 + wr * 16 + gq;
            int b2 = b1 + 8;
#pragma unroll
            for (int j = 0; j < 2; ++j) {
                int col = wc * 16 + j * 8 + t4 * 2;
                int g = n0 + col;
                if (g < GG) {
                    float bi0 = s_bias[col], bi1 = s_bias[col + 1];
                    g_xout[b1 * GG + g]     = acc[j][0] + bi0 + __ldcg(&xkrow[(size_t)b1 * GG + g]);
                    g_xout[b1 * GG + g + 1] = acc[j][1] + bi1 + __ldcg(&xkrow[(size_t)b1 * GG + g + 1]);
                    g_xout[b2 * GG + g]     = acc[j][2] + bi0 + __ldcg(&xkrow[(size_t)b2 * GG + g]);
                    g_xout[b2 * GG + g + 1] = acc[j][3] + bi1 + __ldcg(&xkrow[(size_t)b2 * GG + g + 1]);
                }
            }
        }
        ++seq; gbar(seq);

        // masters (per batch row; blocks 0..127 each handle one row)
        if (bid < BB && tid == 0) { }
        if (tid < BB && bid == 0) { }
        // compute masters: 100 blocks, rows 0..127 -> blocks 0..99 handle rows, rows 100..127 handled by blocks 0..27 (second slot)
        for (int b = bid; b < BB; b += K2_NB) {
            if (tid == 0) {
                const float* row = g_xout + b * GG;
                float m0 = __ldcg(&row[0]), m1 = __ldcg(&row[1]), m2 = __ldcg(&row[2]);
                float v0 = __ldcg(&row[3]), v1 = __ldcg(&row[4]), v2 = __ldcg(&row[5]);
                float mx = fmaxf(m0, fmaxf(m1, m2));
                float e0 = expf(m0 - mx), e1 = expf(m1 - mx), e2 = expf(m2 - mx);
                float inv = 1.f / (e0 + e1 + e2);
                float f0 = e0 * inv, f1 = (e0 + e1) * inv;
                g_dist[t * BB + b] = 1.f - (f0 + f1 + 1.f) * (1.f / 3.f);
            }
        }
        // per-block masters into smem for the rows this block's ew covers:
        // ew indices idx = bid*256+tid + k*100*256 -> rows idx/384. Simpler: all 128 rows.
        if (tid < BB) {
            int b = tid;
            const float* row = g_xout + b * GG;
            float m0 = __ldcg(&row[0]), m1 = __ldcg(&row[1]), m2 = __ldcg(&row[2]);
            float v0 = __ldcg(&row[3]), v1 = __ldcg(&row[4]), v2 = __ldcg(&row[5]);
            float mx = fmaxf(m0, fmaxf(m1, m2));
            float e0 = expf(m0 - mx), e1 = expf(m1 - mx), e2 = expf(m2 - mx);
            float inv = 1.f / (e0 + e1 + e2);
            float f0 = e0 * inv, f1 = (e0 + e1) * inv;
            mx = fmaxf(v0, fmaxf(v1, v2));
            e0 = expf(v0 - mx); e1 = expf(v1 - mx); e2 = expf(v2 - mx);
            inv = 1.f / (e0 + e1 + e2);
            s_mst[tid * 4 + 0] = f0;
            s_mst[tid * 4 + 1] = f1;
            s_mst[tid * 4 + 2] = (e1 + e2) * inv;
            s_mst[tid * 4 + 3] = e2 * inv;
        }
        __syncthreads();
        for (int idx = bid * 256 + tid; idx < BB * HH; idx += K2_NB * 256) {
            int b = idx / HH, i = idx - b * HH;
            int l = i >> 7, c127 = i & 127;
            float fm = (l == 0) ? s_mst[b * 4] : ((l == 1) ? s_mst[b * 4 + 1] : 1.f);
            float im = (l == 0) ? 1.f : ((l == 1) ? s_mst[b * 4 + 2] : s_mst[b * 4 + 3]);
            float ov = fm * im;
            const float* row = g_xout + b * GG;
            float gf = __ldcg(&row[6 + l * 128 + c127]);
            float gi = __ldcg(&row[6 + (3 + l) * 128 + c127]);
            float go = __ldcg(&row[6 + (6 + l) * 128 + c127]);
            float gc = __ldcg(&row[6 + (9 + l) * 128 + c127]);
            float fg = 1.f / (1.f + expf(-gf));
            float ig = 1.f / (1.f + expf(-gi));
            float og = 1.f / (1.f + expf(-go));
            float ci = tanhf(gc);
            float cl = g_c[idx];
            float cn = (ov * fg + fm - ov) * cl + (ov * ig + im - ov) * ci;
            float hn = og * tanhf(cn);
            g_c[idx] = cn;
            size_t hx = (size_t)t * BB * HH + idx;
            g_h[hx] = hn;
            __nv_bfloat16 hh = __float2bfloat16(hn);
            g_hhi[hx] = hh;
            g_hlo[hx] = __float2bfloat16(hn - __bfloat162float(hh));
            g_hf[hx] = __float2half(hn);
        }
        ++seq; gbar(seq);
    }
}

// ---------------- K_dis ----------------
__global__ void k_dis() {
    int idx = blockIdx.x * 256 + threadIdx.x;
    if (idx >= NR) return;
    int t = idx >> 7, b = idx & 127;
    float c[CONVW];
    float cum = 0.f;
#pragma unroll
    for (int k = 0; k < CONVW; ++k) {
        int s = t - (CONVW - 1) + k;
        float d = (s >= 0) ? g_dist[s * BB + b] : 0.f;
        cum += d;
        c[k] = cum;
    }
    float mx = c[0];
#pragma unroll
    for (int k = 1; k < CONVW; ++k) mx = fmaxf(mx, c[k]);
    float sum = 0.f;
#pragma unroll
    for (int k = 0; k < CONVW; ++k) { c[k] = expf(c[k] - mx); sum += c[k]; }
    float inv = 1.f / sum;
#pragma unroll
    for (int k = 0; k < CONVW; ++k) g_dis[(size_t)idx * CONVW + k] = c[k] * inv;
}

// ---------------- K3 GEMM (fp16 single pass, K=384) ----------------
#define KSTEP 32
#define NCH3 (K3K / KSTEP)    /* 12 */
__global__ void __launch_bounds__(256, 2) k3_gemm() {
    __shared__ __align__(128) char sbuf[2][2 * 128 * ROWB];
    const int tid = threadIdx.x;
    const int wid = tid >> 5;
    const int lane = tid & 31;
    const int wm = wid >> 2, wn = wid & 3;
    const int n0 = blockIdx.x * 128;
    const size_t r0 = (size_t)blockIdx.y * 128;
    const int grow = tid >> 1, ghalf = tid & 1;
    uint32_t sA[2], sB[2];
#pragma unroll
    for (int s = 0; s < 2; ++s) {
        sA[s] = smem_u32(&sbuf[s][0]);
        sB[s] = smem_u32(&sbuf[s][128 * ROWB]);
    }
    const int q4 = lane >> 3;
    const uint32_t aoff = (uint32_t)(((q4 & 1) * 8 + (lane & 7)) * ROWB + (q4 >> 1) * 16);
    const uint32_t boff = (uint32_t)((lane & 7) * ROWB + ((lane >> 3) & 1) * 16);

    auto issue = [&](int ch) {
        const int kb = ch * KSTEP;
        const int buf = ch & 1;
        const __half* ga = g_hf + (r0 + grow) * HH + kb + ghalf * 16;
        uint32_t da = sA[buf] + grow * ROWB + ghalf * 32;
        cp16(da, ga); cp16(da + 16, ga + 8);
        const __half* gb = g_wbh + (size_t)(n0 + grow) * K3K + kb + ghalf * 16;
        uint32_t db = sB[buf] + grow * ROWB + ghalf * 32;
        cp16(db, gb); cp16(db + 16, gb + 8);
        asm volatile("cp.async.commit_group;");
    };
    issue(0); issue(1);
    float c[4][4][4] = {};
    for (int ch = 0; ch < NCH3; ++ch) {
        if (ch == NCH3 - 1) asm volatile("cp.async.wait_group 0;");
        else                asm volatile("cp.async.wait_group 1;");
        __syncthreads();
        const int buf = ch & 1;
        const uint32_t abase = sA[buf] + (wm * 64) * ROWB + aoff;
        const uint32_t bbase = sB[buf] + (wn * 32) * ROWB + boff;
#pragma unroll
        for (int s = 0; s < 2; ++s) {
            uint32_t a[4][4];
#pragma unroll
            for (int i = 0; i < 4; ++i) {
                asm volatile("ldmatrix.sync.aligned.m8n8.x4.shared.b16 {%0,%1,%2,%3}, [%4];"
                             : "=r"(a[i][0]), "=r"(a[i][1]), "=r"(a[i][2]), "=r"(a[i][3])
                             : "r"(abase + i * 16 * ROWB + s * 32));
            }
            uint32_t bfr[4][2];
#pragma unroll
            for (int j = 0; j < 4; ++j) {
                asm volatile("ldmatrix.sync.aligned.m8n8.x2.shared.b16 {%0,%1}, [%2];"
                             : "=r"(bfr[j][0]), "=r"(bfr[j][1])
                             : "r"(bbase + j * 8 * ROWB + s * 32));
            }
#pragma unroll
            for (int i = 0; i < 4; ++i)
#pragma unroll
                for (int j = 0; j < 4; ++j)
                    asm volatile(
                        "mma.sync.aligned.m16n8k16.row.col.f32.f16.f16.f32 "
                        "{%0,%1,%2,%3}, {%4,%5,%6,%7}, {%8,%9}, {%0,%1,%2,%3};"
                        : "+f"(c[i][j][0]), "+f"(c[i][j][1]), "+f"(c[i][j][2]), "+f"(c[i][j][3])
                        : "r"(a[i][0]), "r"(a[i][1]), "r"(a[i][2]), "r"(a[i][3]),
                          "r"(bfr[j][0]), "r"(bfr[j][1]));
        }
        __syncthreads();
        if (ch + 2 < NCH3) issue(ch + 2);
    }
    const int gq = lane >> 2, t4 = lane & 3;
#pragma unroll
    for (int i = 0; i < 4; ++i) {
        size_t row = r0 + wm * 64 + i * 16 + gq;
        float* dst0 = g_A + row * NN + n0 + wn * 32 + t4 * 2;
        float* dst1 = g_A + (row + 8) * NN + n0 + wn * 32 + t4 * 2;
#pragma unroll
        for (int j = 0; j < 4; ++j) {
            *reinterpret_cast<float2*>(dst0 + j * 8) = make_float2(c[i][j][0], c[i][j][1]);
            *reinterpret_cast<float2*>(dst1 + j * 8) = make_float2(c[i][j][2], c[i][j][3]);
        }
    }
}

// ---------------- K4: gather + theme MLP + final output (fused) ----------------
__global__ void __launch_bounds__(256) k4_out(const float* __restrict__ Ws,
                                              const float* __restrict__ bs,
                                              const float* __restrict__ Wrs,
                                              const float* __restrict__ brs,
                                              const float* __restrict__ bc,
                                              float* __restrict__ out) {
    __shared__ float s_mh[16][HH];
    __shared__ float s_q[16][HSS];
    __shared__ float s_dis2[16][10];
    const int tid = threadIdx.x;
    const int r0 = blockIdx.x * 16;
    const int t = r0 >> 7, b0 = r0 & 127;
    for (int lin = tid; lin < 160; lin += 256) {
        int rr = lin / 10, k = lin % 10;
        s_dis2[rr][k] = g_dis[(size_t)(r0 + rr) * CONVW + k];
    }
    __syncthreads();
    for (int idx = tid; idx < 16 * HH; idx += 256) {
        int rr = idx / HH, i = idx - rr * HH;
        float acc = 0.f;
#pragma unroll
        for (int k = 0; k < CONVW; ++k) {
            int s = t - (CONVW - 1) + k;
            if (s >= 0)
                acc += s_dis2[rr][k] * g_h[((size_t)s * BB + b0 + rr) * HH + i];
        }
        s_mh[rr][i] = acc * (1.f / CONVW);
    }
    __syncthreads();
    for (int idx = tid; idx < 16 * HSS; idx += 256) {
        int rr = idx >> 6, j = idx & 63;
        float acc = bs[j];
        for (int i = 0; i < HH; ++i) acc += s_mh[rr][i] * Ws[i * HSS + j];
        s_q[rr][j] = fmaxf(acc, 0.f);
    }
    __syncthreads();
    for (int idx = tid; idx < 16 * HH; idx += 256) {
        int rr = idx / HH, o = idx - rr * HH;
        float acc = brs[o];
#pragma unroll 8
        for (int j = 0; j < HSS; ++j) acc += s_q[rr][j] * Wrs[j * HH + o];
        float theme = 1.f / (1.f + expf(-acc));
        int b = b0 + rr;
        // inline gather: conv = bc + sum_k dis * A
        float conv = bc[o];
#pragma unroll
        for (int k = 0; k < CONVW; ++k) {
            int s = t - (CONVW - 1) + k;
            if (s >= 0)
                conv += s_dis2[rr][k] * g_A[((size_t)s * BB + b) * NN + (size_t)k * HH + o];
        }
        out[((size_t)b * TT + t) * HH + o] =
            theme * conv + g_h[((size_t)t * BB + b) * HH + o];
    }
}

// ---------------- entry ----------------
extern "C" void kernel_launch(void* const* d_in, const int* in_sizes, int n_in,
                              void* d_out, int out_size) {
    (void)in_sizes; (void)n_in; (void)out_size;
    const float* x   = (const float*)d_in[0];
    const float* Wk  = (const float*)d_in[2];
    const float* bk  = (const float*)d_in[3];
    const float* Wr  = (const float*)d_in[4];
    const float* br  = (const float*)d_in[5];
    const float* Ws  = (const float*)d_in[6];
    const float* bs  = (const float*)d_in[7];
    const float* Wrs = (const float*)d_in[8];
    const float* brs = (const float*)d_in[9];
    const float* Wc  = (const float*)d_in[10];
    const float* bc  = (const float*)d_in[11];
    float* out = (float*)d_out;

    cudaFuncSetAttribute(k2_recurrent, cudaFuncAttributeMaxDynamicSharedMemorySize, K2_SMEM);

    k_prep_w<<<(int)(((size_t)NN * K3K + 255) / 256), 256>>>(Wc);
    k_prep_wk<<<(int)(((size_t)K1NP * K1K + 255) / 256), 256>>>(Wk);
    k_prep_wr<<<(int)(((size_t)K2NP * HH + 255) / 256), 256>>>(Wr);
    k_half_x<<<(int)(((size_t)NR * DD / 4 + 255) / 256), 256>>>(x);
    k1_gemm<<<dim3(13, 512), 256>>>(Wk, bk);
    k2_recurrent<<<K2_NB, 256, K2_SMEM>>>(Wr, br);
    k_dis<<<(NR + 255) / 256, 256>>>();
    k3_gemm<<<dim3(30, 512), 256>>>();
    k4_out<<<4096, 256>>>(Ws, bs, Wrs, brs, bc, out);
}

// round 12
// speedup vs baseline: 1.9927x; 1.1582x over previous
#include <cuda_runtime.h>
#include <cuda_bf16.h>
#include <cuda_fp16.h>
#include <cstdint>
#include <math.h>

#define BB 128
#define TT 512
#define DD 128
#define HH 384
#define GG 1542
#define CONVW 10
#define HSS 64
#define NR (TT * BB)          /* 65536 rows */
#define NN 3840               /* K3 N = CONVW * HH */
#define K3K 384               /* K3 K (fp16 single pass) */
#define K1K 128               /* K1 K (fp16 single pass) */
#define K1NP 1664             /* K1 N padded */
#define K2NP 1600             /* K2 N padded */

// ---------------- static device scratch ----------------
__device__ float g_xk[(size_t)NR * GG];
__device__ float g_xout[BB * GG];
__device__ float g_h[(size_t)NR * HH];
__device__ float g_c[BB * HH];
__device__ float g_dist[NR];
__device__ float g_dis[NR * CONVW];
__device__ float g_A[(size_t)NR * NN];
__device__ __half g_hf[(size_t)NR * HH];           // h fp16 (K2 A + K3 A)
__device__ __half g_wbh[(size_t)NN * K3K];         // K3 B (fp16)
__device__ __half g_xh[(size_t)NR * DD];           // K1 A (fp16)
__device__ __half g_wkh[(size_t)K1NP * K1K];       // K1 B (fp16)
__device__ __half g_wrh[(size_t)K2NP * HH];        // K2 B (fp16)
__device__ volatile unsigned g_flags[128];
__device__ volatile unsigned g_relsd;

// ---------------- helpers ----------------
__device__ __forceinline__ uint32_t smem_u32(const void* p) {
    uint32_t a;
    asm("{ .reg .u64 t; cvta.to.shared.u64 t, %1; cvt.u32.u64 %0, t; }" : "=r"(a) : "l"(p));
    return a;
}
__device__ __forceinline__ void cp16(uint32_t s, const void* g) {
    asm volatile("cp.async.cg.shared.global [%0], [%1], 16;" :: "r"(s), "l"(g));
}

#define K2_NB 100

// flag-based grid barrier (replay-safe via monotonic release counter)
__device__ __forceinline__ void gbar(unsigned seq) {
    __threadfence();
    __syncthreads();
    if (blockIdx.x == 0) {
        if (threadIdx.x > 0 && threadIdx.x < K2_NB) {
            while (g_flags[threadIdx.x] < seq) { __nanosleep(40); }
        }
        __syncthreads();
        if (threadIdx.x == 0) g_relsd = seq;
        __syncthreads();
    } else {
        if (threadIdx.x == 0) {
            g_flags[blockIdx.x] = seq;
            while (g_relsd < seq) { __nanosleep(40); }
            __threadfence();
        }
        __syncthreads();
    }
}

// ---------------- prep kernels ----------------
__global__ void __launch_bounds__(256) k_half_x(const float* __restrict__ x) {
    size_t idx = (size_t)blockIdx.x * 256 + threadIdx.x;   // float4 index
    if (idx >= (size_t)NR * DD / 4) return;
    size_t e = idx * 4;
    int d4 = (int)(e & 127);
    int r = (int)(e >> 7);
    int t = r >> 7, b = r & 127;
    float4 v = *reinterpret_cast<const float4*>(x + ((size_t)b * TT + t) * DD + d4);
    __half2* dst = reinterpret_cast<__half2*>(g_xh) + idx * 2;
    dst[0] = __floats2half2_rn(v.x, v.y);
    dst[1] = __floats2half2_rn(v.z, v.w);
}

__global__ void __launch_bounds__(256) k_prep_wk(const float* __restrict__ Wk) {
    size_t idx = (size_t)blockIdx.x * 256 + threadIdx.x;
    if (idx >= (size_t)K1NP * K1K) return;
    int i = (int)(idx % K1K);
    int n = (int)(idx / K1K);
    float w = (n < GG) ? Wk[(size_t)i * GG + n] : 0.f;
    g_wkh[idx] = __float2half(w);
}

__global__ void __launch_bounds__(256) k_prep_wr(const float* __restrict__ Wr) {
    size_t idx = (size_t)blockIdx.x * 256 + threadIdx.x;
    if (idx >= (size_t)K2NP * HH) return;
    int k = (int)(idx % HH);
    int n = (int)(idx / HH);
    float w = (n < GG) ? Wr[(size_t)k * GG + n] : 0.f;
    g_wrh[idx] = __float2half(w);
}

__global__ void __launch_bounds__(256) k_prep_w(const float* __restrict__ Wc) {
    size_t idx = (size_t)blockIdx.x * 256 + threadIdx.x;
    if (idx >= (size_t)NN * K3K) return;
    int i = (int)(idx % K3K);
    int n = (int)(idx / K3K);
    int k = n / HH, o = n - k * HH;
    g_wbh[idx] = __float2half(Wc[((size_t)o * HH + i) * CONVW + k]);
}

// ---------------- K1 GEMM: g_xk = [x,1]@Wk + bk via fp16 HMMA ----------------
#define ROWB 80
__global__ void __launch_bounds__(256, 2) k1_gemm(const float* __restrict__ Wk,
                                                  const float* __restrict__ bk) {
    __shared__ __align__(128) char sbuf[2][2 * 128 * ROWB];
    const int tid = threadIdx.x;
    const int wid = tid >> 5;
    const int lane = tid & 31;
    const int wm = wid >> 2, wn = wid & 3;
    const int n0 = blockIdx.x * 128;
    const size_t r0 = (size_t)blockIdx.y * 128;
    const int grow = tid >> 1, ghalf = tid & 1;

    uint32_t sA[2], sB[2];
#pragma unroll
    for (int s = 0; s < 2; ++s) {
        sA[s] = smem_u32(&sbuf[s][0]);
        sB[s] = smem_u32(&sbuf[s][128 * ROWB]);
    }
    const int q4 = lane >> 3;
    const uint32_t aoff = (uint32_t)(((q4 & 1) * 8 + (lane & 7)) * ROWB + (q4 >> 1) * 16);
    const uint32_t boff = (uint32_t)((lane & 7) * ROWB + ((lane >> 3) & 1) * 16);

    auto issue = [&](int ch) {
        const int kb = ch * 32;
        const int buf = ch & 1;
        const __half* ga = g_xh + (r0 + grow) * DD + kb + ghalf * 16;
        uint32_t da = sA[buf] + grow * ROWB + ghalf * 32;
        cp16(da, ga); cp16(da + 16, ga + 8);
        const __half* gb = g_wkh + (size_t)(n0 + grow) * K1K + kb + ghalf * 16;
        uint32_t db = sB[buf] + grow * ROWB + ghalf * 32;
        cp16(db, gb); cp16(db + 16, gb + 8);
        asm volatile("cp.async.commit_group;");
    };
    issue(0); issue(1);
    float c[4][4][4] = {};
    const int NCH1 = K1K / 32;   // 4
    for (int ch = 0; ch < NCH1; ++ch) {
        if (ch == NCH1 - 1) asm volatile("cp.async.wait_group 0;");
        else                asm volatile("cp.async.wait_group 1;");
        __syncthreads();
        const int buf = ch & 1;
        const uint32_t abase = sA[buf] + (wm * 64) * ROWB + aoff;
        const uint32_t bbase = sB[buf] + (wn * 32) * ROWB + boff;
#pragma unroll
        for (int s = 0; s < 2; ++s) {
            uint32_t a[4][4];
#pragma unroll
            for (int i = 0; i < 4; ++i) {
                asm volatile("ldmatrix.sync.aligned.m8n8.x4.shared.b16 {%0,%1,%2,%3}, [%4];"
                             : "=r"(a[i][0]), "=r"(a[i][1]), "=r"(a[i][2]), "=r"(a[i][3])
                             : "r"(abase + i * 16 * ROWB + s * 32));
            }
            uint32_t bf[4][2];
#pragma unroll
            for (int j = 0; j < 4; ++j) {
                asm volatile("ldmatrix.sync.aligned.m8n8.x2.shared.b16 {%0,%1}, [%2];"
                             : "=r"(bf[j][0]), "=r"(bf[j][1])
                             : "r"(bbase + j * 8 * ROWB + s * 32));
            }
#pragma unroll
            for (int i = 0; i < 4; ++i)
#pragma unroll
                for (int j = 0; j < 4; ++j)
                    asm volatile(
                        "mma.sync.aligned.m16n8k16.row.col.f32.f16.f16.f32 "
                        "{%0,%1,%2,%3}, {%4,%5,%6,%7}, {%8,%9}, {%0,%1,%2,%3};"
                        : "+f"(c[i][j][0]), "+f"(c[i][j][1]), "+f"(c[i][j][2]), "+f"(c[i][j][3])
                        : "r"(a[i][0]), "r"(a[i][1]), "r"(a[i][2]), "r"(a[i][3]),
                          "r"(bf[j][0]), "r"(bf[j][1]));
        }
        __syncthreads();
        if (ch + 2 < NCH1) issue(ch + 2);
    }
    const int gq = lane >> 2, t4 = lane & 3;
#pragma unroll
    for (int i = 0; i < 4; ++i) {
        size_t row = r0 + wm * 64 + i * 16 + gq;
#pragma unroll
        for (int j = 0; j < 4; ++j) {
            int g = n0 + wn * 32 + j * 8 + t4 * 2;
            if (g < GG) {
                float b0v = Wk[(size_t)DD * GG + g] + bk[g];
                float b1v = Wk[(size_t)DD * GG + g + 1] + bk[g + 1];
                g_xk[row * GG + g]           = c[i][j][0] + b0v;
                g_xk[row * GG + g + 1]       = c[i][j][1] + b1v;
                g_xk[(row + 8) * GG + g]     = c[i][j][2] + b0v;
                g_xk[(row + 8) * GG + g + 1] = c[i][j][3] + b1v;
            }
        }
    }
}

// ---------------- K2: persistent fp16 HMMA recurrent scan ----------------
// 100 blocks = 4 m-tiles (32 rows) x 25 n-tiles (64 cols). Wr fp16 cached in smem.
#define K2_PAD 784
#define K2_SM_W 0
#define K2_SM_A 50176
#define K2_SM_MST 75264
#define K2_SM_BIAS 77312
#define K2_SMEM 77568

__global__ void __launch_bounds__(256) k2_recurrent(const float* __restrict__ Wr,
                                                    const float* __restrict__ br) {
    extern __shared__ __align__(16) char s2[];
    const int tid = threadIdx.x;
    const int bid = blockIdx.x;
    const int mt = bid / 25, nt = bid % 25;
    const int bm0 = mt * 32;
    const int n0 = nt * 64;
    const unsigned base = g_relsd;

    // persistent B load (fp16) + bias: 64 rows x 48 16B-chunks (= HH fp16)
    for (int q = tid; q < 64 * 48; q += 256) {
        int row = q / 48, cc = q % 48;
        *reinterpret_cast<uint4*>(s2 + K2_SM_W + row * K2_PAD + cc * 16) =
            *reinterpret_cast<const uint4*>(g_wrh + (size_t)(n0 + row) * HH + cc * 8);
    }
    float* s_bias = reinterpret_cast<float*>(s2 + K2_SM_BIAS);
    for (int n = tid; n < 64; n += 256) {
        int g = n0 + n;
        s_bias[n] = (g < GG) ? (Wr[(size_t)HH * GG + g] + br[g]) : 0.f;
    }
    float* s_mst = reinterpret_cast<float*>(s2 + K2_SM_MST);
    for (int i = bid * 256 + tid; i < BB * HH; i += K2_NB * 256) g_c[i] = 0.f;
    unsigned seq = base + 1;
    gbar(seq);

    const int wid = tid >> 5, lane = tid & 31;
    const int wr = wid >> 2, wc = wid & 3;
    const int q4 = lane >> 3;
    const uint32_t fo = (uint32_t)(((q4 & 1) * 8 + (lane & 7)) * K2_PAD + (q4 >> 1) * 16);
    const uint32_t sbase = smem_u32(s2);
    const uint32_t a_base = sbase + K2_SM_A + wr * 16 * K2_PAD + fo;
    const uint32_t b_base = sbase + K2_SM_W + wc * 16 * K2_PAD + fo;
    const int gq = lane >> 2, t4 = lane & 3;

    for (int t = 0; t < TT; ++t) {
        float acc[2][4] = {};
        if (t > 0) {
            const size_t rb = (size_t)(t - 1) * BB + bm0;
            // A tile: 32 rows x 48 16B-chunks (fp16 h)
            for (int q = tid; q < 32 * 48; q += 256) {
                int row = q / 48, cc = q % 48;
                uint4 v = __ldcg(reinterpret_cast<const uint4*>(
                    g_hf + (rb + row) * HH + cc * 8));
                *reinterpret_cast<uint4*>(s2 + K2_SM_A + row * K2_PAD + cc * 16) = v;
            }
            __syncthreads();
#pragma unroll
            for (int ki = 0; ki < 24; ++ki) {
                uint32_t a[4], b[4];
                asm volatile("ldmatrix.sync.aligned.m8n8.x4.shared.b16 {%0,%1,%2,%3}, [%4];"
                             : "=r"(a[0]), "=r"(a[1]), "=r"(a[2]), "=r"(a[3])
                             : "r"(a_base + ki * 32));
                asm volatile("ldmatrix.sync.aligned.m8n8.x4.shared.b16 {%0,%1,%2,%3}, [%4];"
                             : "=r"(b[0]), "=r"(b[1]), "=r"(b[2]), "=r"(b[3])
                             : "r"(b_base + ki * 32));
                asm volatile(
                    "mma.sync.aligned.m16n8k16.row.col.f32.f16.f16.f32 "
                    "{%0,%1,%2,%3}, {%4,%5,%6,%7}, {%8,%9}, {%0,%1,%2,%3};"
                    : "+f"(acc[0][0]), "+f"(acc[0][1]), "+f"(acc[0][2]), "+f"(acc[0][3])
                    : "r"(a[0]), "r"(a[1]), "r"(a[2]), "r"(a[3]),
                      "r"(b[0]), "r"(b[2]));
                asm volatile(
                    "mma.sync.aligned.m16n8k16.row.col.f32.f16.f16.f32 "
                    "{%0,%1,%2,%3}, {%4,%5,%6,%7}, {%8,%9}, {%0,%1,%2,%3};"
                    : "+f"(acc[1][0]), "+f"(acc[1][1]), "+f"(acc[1][2]), "+f"(acc[1][3])
                    : "r"(a[0]), "r"(a[1]), "r"(a[2]), "r"(a[3]),
                      "r"(b[1]), "r"(b[3]));
            }
        }
        // epilogue -> g_xout
        {
            const float* xkrow = g_xk + (size_t)t * BB * GG;
            int b1 = bm0 + wr * 16 + gq;
            int b2 = b1 + 8;
#pragma unroll
            for (int j = 0; j < 2; ++j) {
                int col = wc * 16 + j * 8 + t4 * 2;
                int g = n0 + col;
                if (g < GG) {
                    float bi0 = s_bias[col], bi1 = s_bias[col + 1];
                    g_xout[b1 * GG + g]     = acc[j][0] + bi0 + __ldcg(&xkrow[(size_t)b1 * GG + g]);
                    g_xout[b1 * GG + g + 1] = acc[j][1] + bi1 + __ldcg(&xkrow[(size_t)b1 * GG + g + 1]);
                    g_xout[b2 * GG + g]     = acc[j][2] + bi0 + __ldcg(&xkrow[(size_t)b2 * GG + g]);
                    g_xout[b2 * GG + g + 1] = acc[j][3] + bi1 + __ldcg(&xkrow[(size_t)b2 * GG + g + 1]);
                }
            }
        }
        ++seq; gbar(seq);

        // masters (per batch row; 4 warps compute all 128 rows)
        if (tid < BB) {
            int b = tid;
            const float* row = g_xout + b * GG;
            float m0 = __ldcg(&row[0]), m1 = __ldcg(&row[1]), m2 = __ldcg(&row[2]);
            float v0 = __ldcg(&row[3]), v1 = __ldcg(&row[4]), v2 = __ldcg(&row[5]);
            float mx = fmaxf(m0, fmaxf(m1, m2));
            float e0 = expf(m0 - mx), e1 = expf(m1 - mx), e2 = expf(m2 - mx);
            float inv = 1.f / (e0 + e1 + e2);
            float f0 = e0 * inv, f1 = (e0 + e1) * inv;
            mx = fmaxf(v0, fmaxf(v1, v2));
            e0 = expf(v0 - mx); e1 = expf(v1 - mx); e2 = expf(v2 - mx);
            inv = 1.f / (e0 + e1 + e2);
            s_mst[b * 4 + 0] = f0;
            s_mst[b * 4 + 1] = f1;
            s_mst[b * 4 + 2] = (e1 + e2) * inv;
            s_mst[b * 4 + 3] = e2 * inv;
            if (bid == 0) g_dist[t * BB + b] = 1.f - (f0 + f1 + 1.f) * (1.f / 3.f);
        }
        __syncthreads();
        for (int idx = bid * 256 + tid; idx < BB * HH; idx += K2_NB * 256) {
            int b = idx / HH, i = idx - b * HH;
            int l = i >> 7, c127 = i & 127;
            float fm = (l == 0) ? s_mst[b * 4] : ((l == 1) ? s_mst[b * 4 + 1] : 1.f);
            float im = (l == 0) ? 1.f : ((l == 1) ? s_mst[b * 4 + 2] : s_mst[b * 4 + 3]);
            float ov = fm * im;
            const float* row = g_xout + b * GG;
            float gf = __ldcg(&row[6 + l * 128 + c127]);
            float gi = __ldcg(&row[6 + (3 + l) * 128 + c127]);
            float go = __ldcg(&row[6 + (6 + l) * 128 + c127]);
            float gc = __ldcg(&row[6 + (9 + l) * 128 + c127]);
            float fg = 1.f / (1.f + expf(-gf));
            float ig = 1.f / (1.f + expf(-gi));
            float og = 1.f / (1.f + expf(-go));
            float ci = tanhf(gc);
            float cl = g_c[idx];
            float cn = (ov * fg + fm - ov) * cl + (ov * ig + im - ov) * ci;
            float hn = og * tanhf(cn);
            g_c[idx] = cn;
            size_t hx = (size_t)t * BB * HH + idx;
            g_h[hx] = hn;
            g_hf[hx] = __float2half(hn);
        }
        ++seq; gbar(seq);
    }
}

// ---------------- K_dis ----------------
__global__ void k_dis() {
    int idx = blockIdx.x * 256 + threadIdx.x;
    if (idx >= NR) return;
    int t = idx >> 7, b = idx & 127;
    float c[CONVW];
    float cum = 0.f;
#pragma unroll
    for (int k = 0; k < CONVW; ++k) {
        int s = t - (CONVW - 1) + k;
        float d = (s >= 0) ? g_dist[s * BB + b] : 0.f;
        cum += d;
        c[k] = cum;
    }
    float mx = c[0];
#pragma unroll
    for (int k = 1; k < CONVW; ++k) mx = fmaxf(mx, c[k]);
    float sum = 0.f;
#pragma unroll
    for (int k = 0; k < CONVW; ++k) { c[k] = expf(c[k] - mx); sum += c[k]; }
    float inv = 1.f / sum;
#pragma unroll
    for (int k = 0; k < CONVW; ++k) g_dis[(size_t)idx * CONVW + k] = c[k] * inv;
}

// ---------------- K3 GEMM (fp16 single pass, K=384) ----------------
#define KSTEP 32
#define NCH3 (K3K / KSTEP)    /* 12 */
__global__ void __launch_bounds__(256, 2) k3_gemm() {
    __shared__ __align__(128) char sbuf[2][2 * 128 * ROWB];
    const int tid = threadIdx.x;
    const int wid = tid >> 5;
    const int lane = tid & 31;
    const int wm = wid >> 2, wn = wid & 3;
    const int n0 = blockIdx.x * 128;
    const size_t r0 = (size_t)blockIdx.y * 128;
    const int grow = tid >> 1, ghalf = tid & 1;
    uint32_t sA[2], sB[2];
#pragma unroll
    for (int s = 0; s < 2; ++s) {
        sA[s] = smem_u32(&sbuf[s][0]);
        sB[s] = smem_u32(&sbuf[s][128 * ROWB]);
    }
    const int q4 = lane >> 3;
    const uint32_t aoff = (uint32_t)(((q4 & 1) * 8 + (lane & 7)) * ROWB + (q4 >> 1) * 16);
    const uint32_t boff = (uint32_t)((lane & 7) * ROWB + ((lane >> 3) & 1) * 16);

    auto issue = [&](int ch) {
        const int kb = ch * KSTEP;
        const int buf = ch & 1;
        const __half* ga = g_hf + (r0 + grow) * HH + kb + ghalf * 16;
        uint32_t da = sA[buf] + grow * ROWB + ghalf * 32;
        cp16(da, ga); cp16(da + 16, ga + 8);
        const __half* gb = g_wbh + (size_t)(n0 + grow) * K3K + kb + ghalf * 16;
        uint32_t db = sB[buf] + grow * ROWB + ghalf * 32;
        cp16(db, gb); cp16(db + 16, gb + 8);
        asm volatile("cp.async.commit_group;");
    };
    issue(0); issue(1);
    float c[4][4][4] = {};
    for (int ch = 0; ch < NCH3; ++ch) {
        if (ch == NCH3 - 1) asm volatile("cp.async.wait_group 0;");
        else                asm volatile("cp.async.wait_group 1;");
        __syncthreads();
        const int buf = ch & 1;
        const uint32_t abase = sA[buf] + (wm * 64) * ROWB + aoff;
        const uint32_t bbase = sB[buf] + (wn * 32) * ROWB + boff;
#pragma unroll
        for (int s = 0; s < 2; ++s) {
            uint32_t a[4][4];
#pragma unroll
            for (int i = 0; i < 4; ++i) {
                asm volatile("ldmatrix.sync.aligned.m8n8.x4.shared.b16 {%0,%1,%2,%3}, [%4];"
                             : "=r"(a[i][0]), "=r"(a[i][1]), "=r"(a[i][2]), "=r"(a[i][3])
                             : "r"(abase + i * 16 * ROWB + s * 32));
            }
            uint32_t bfr[4][2];
#pragma unroll
            for (int j = 0; j < 4; ++j) {
                asm volatile("ldmatrix.sync.aligned.m8n8.x2.shared.b16 {%0,%1}, [%2];"
                             : "=r"(bfr[j][0]), "=r"(bfr[j][1])
                             : "r"(bbase + j * 8 * ROWB + s * 32));
            }
#pragma unroll
            for (int i = 0; i < 4; ++i)
#pragma unroll
                for (int j = 0; j < 4; ++j)
                    asm volatile(
                        "mma.sync.aligned.m16n8k16.row.col.f32.f16.f16.f32 "
                        "{%0,%1,%2,%3}, {%4,%5,%6,%7}, {%8,%9}, {%0,%1,%2,%3};"
                        : "+f"(c[i][j][0]), "+f"(c[i][j][1]), "+f"(c[i][j][2]), "+f"(c[i][j][3])
                        : "r"(a[i][0]), "r"(a[i][1]), "r"(a[i][2]), "r"(a[i][3]),
                          "r"(bfr[j][0]), "r"(bfr[j][1]));
        }
        __syncthreads();
        if (ch + 2 < NCH3) issue(ch + 2);
    }
    const int gq = lane >> 2, t4 = lane & 3;
#pragma unroll
    for (int i = 0; i < 4; ++i) {
        size_t row = r0 + wm * 64 + i * 16 + gq;
        float* dst0 = g_A + row * NN + n0 + wn * 32 + t4 * 2;
        float* dst1 = g_A + (row + 8) * NN + n0 + wn * 32 + t4 * 2;
#pragma unroll
        for (int j = 0; j < 4; ++j) {
            *reinterpret_cast<float2*>(dst0 + j * 8) = make_float2(c[i][j][0], c[i][j][1]);
            *reinterpret_cast<float2*>(dst1 + j * 8) = make_float2(c[i][j][2], c[i][j][3]);
        }
    }
}

// ---------------- K4: gather + theme MLP + final output (fused) ----------------
__global__ void __launch_bounds__(256) k4_out(const float* __restrict__ Ws,
                                              const float* __restrict__ bs,
                                              const float* __restrict__ Wrs,
                                              const float* __restrict__ brs,
                                              const float* __restrict__ bc,
                                              float* __restrict__ out) {
    __shared__ float s_mh[16][HH];
    __shared__ float s_q[16][HSS];
    __shared__ float s_dis2[16][10];
    const int tid = threadIdx.x;
    const int r0 = blockIdx.x * 16;
    const int t = r0 >> 7, b0 = r0 & 127;
    for (int lin = tid; lin < 160; lin += 256) {
        int rr = lin / 10, k = lin % 10;
        s_dis2[rr][k] = g_dis[(size_t)(r0 + rr) * CONVW + k];
    }
    __syncthreads();
    for (int idx = tid; idx < 16 * HH; idx += 256) {
        int rr = idx / HH, i = idx - rr * HH;
        float acc = 0.f;
#pragma unroll
        for (int k = 0; k < CONVW; ++k) {
            int s = t - (CONVW - 1) + k;
            if (s >= 0)
                acc += s_dis2[rr][k] * g_h[((size_t)s * BB + b0 + rr) * HH + i];
        }
        s_mh[rr][i] = acc * (1.f / CONVW);
    }
    __syncthreads();
    for (int idx = tid; idx < 16 * HSS; idx += 256) {
        int rr = idx >> 6, j = idx & 63;
        float acc = bs[j];
        for (int i = 0; i < HH; ++i) acc += s_mh[rr][i] * Ws[i * HSS + j];
        s_q[rr][j] = fmaxf(acc, 0.f);
    }
    __syncthreads();
    for (int idx = tid; idx < 16 * HH; idx += 256) {
        int rr = idx / HH, o = idx - rr * HH;
        float acc = brs[o];
#pragma unroll 8
        for (int j = 0; j < HSS; ++j) acc += s_q[rr][j] * Wrs[j * HH + o];
        float theme = 1.f / (1.f + expf(-acc));
        int b = b0 + rr;
        // inline gather: conv = bc + sum_k dis * A
        float conv = bc[o];
#pragma unroll
        for (int k = 0; k < CONVW; ++k) {
            int s = t - (CONVW - 1) + k;
            if (s >= 0)
                conv += s_dis2[rr][k] * g_A[((size_t)s * BB + b) * NN + (size_t)k * HH + o];
        }
        out[((size_t)b * TT + t) * HH + o] =
            theme * conv + g_h[((size_t)t * BB + b) * HH + o];
    }
}

// ---------------- entry ----------------
extern "C" void kernel_launch(void* const* d_in, const int* in_sizes, int n_in,
                              void* d_out, int out_size) {
    (void)in_sizes; (void)n_in; (void)out_size;
    const float* x   = (const float*)d_in[0];
    const float* Wk  = (const float*)d_in[2];
    const float* bk  = (const float*)d_in[3];
    const float* Wr  = (const float*)d_in[4];
    const float* br  = (const float*)d_in[5];
    const float* Ws  = (const float*)d_in[6];
    const float* bs  = (const float*)d_in[7];
    const float* Wrs = (const float*)d_in[8];
    const float* brs = (const float*)d_in[9];
    const float* Wc  = (const float*)d_in[10];
    const float* bc  = (const float*)d_in[11];
    float* out = (float*)d_out;

    cudaFuncSetAttribute(k2_recurrent, cudaFuncAttributeMaxDynamicSharedMemorySize, K2_SMEM);

    k_prep_w<<<(int)(((size_t)NN * K3K + 255) / 256), 256>>>(Wc);
    k_prep_wk<<<(int)(((size_t)K1NP * K1K + 255) / 256), 256>>>(Wk);
    k_prep_wr<<<(int)(((size_t)K2NP * HH + 255) / 256), 256>>>(Wr);
    k_half_x<<<(int)(((size_t)NR * DD / 4 + 255) / 256), 256>>>(x);
    k1_gemm<<<dim3(13, 512), 256>>>(Wk, bk);
    k2_recurrent<<<K2_NB, 256, K2_SMEM>>>(Wr, br);
    k_dis<<<(NR + 255) / 256, 256>>>();
    k3_gemm<<<dim3(30, 512), 256>>>();
    k4_out<<<4096, 256>>>(Ws, bs, Wrs, brs, bc, out);
}

// round 15
// speedup vs baseline: 2.1374x; 1.0726x over previous
#include <cuda_runtime.h>
#include <cuda_bf16.h>
#include <cuda_fp16.h>
#include <cstdint>
#include <math.h>

#define BB 128
#define TT 512
#define DD 128
#define HH 384
#define GG 1542
#define CONVW 10
#define HSS 64
#define NR (TT * BB)
#define NN 3840
#define K3K 384
#define K1K 128
#define K1NP 1664
#define K2NP 1600

// ---------------- static device scratch ----------------
__device__ float g_xk[(size_t)NR * GG];
__device__ float g_xout[BB * GG];
__device__ float g_dist[NR];
__device__ float g_dis[NR * CONVW];
__device__ float g_A[(size_t)NR * NN];
__device__ __half g_hf[(size_t)NR * HH];           // h fp16 (K2 state + K3/K4 input)
__device__ __half g_wbh[(size_t)NN * K3K];         // K3 B
__device__ __half g_xh[(size_t)NR * DD];           // K1 A
__device__ __half g_wkh[(size_t)K1NP * K1K];       // K1 B
__device__ __half g_wrh[(size_t)K2NP * HH];        // K2 B
__device__ volatile unsigned g_f2[4][32];          // per-group flags (one line/group)
__device__ volatile unsigned g_r2[4][32];          // per-group release word

// ---------------- helpers ----------------
__device__ __forceinline__ uint32_t smem_u32(const void* p) {
    uint32_t a;
    asm("{ .reg .u64 t; cvta.to.shared.u64 t, %1; cvt.u32.u64 %0, t; }" : "=r"(a) : "l"(p));
    return a;
}
__device__ __forceinline__ void cp16(uint32_t s, const void* g) {
    asm volatile("cp.async.cg.shared.global [%0], [%1], 16;" :: "r"(s), "l"(g));
}

// per-group leader-poll barrier: 25 blocks; leader (nt==0) polls 24 flags,
// releases one word; followers write own flag, poll release. Replay-safe
// via monotonic sequence.
__device__ __forceinline__ void k2bar(int grp, int nt, unsigned seq) {
    __threadfence();
    __syncthreads();
    if (nt == 0) {
        if (threadIdx.x >= 1 && threadIdx.x < 25) {
            while (g_f2[grp][threadIdx.x] < seq) { __nanosleep(40); }
        }
        __syncthreads();
        if (threadIdx.x == 0) g_r2[grp][0] = seq;
        __syncthreads();
    } else {
        if (threadIdx.x == 0) {
            g_f2[grp][nt] = seq;
            while (g_r2[grp][0] < seq) { __nanosleep(40); }
            __threadfence();
        }
        __syncthreads();
    }
}

// ---------------- prep kernels ----------------
__global__ void __launch_bounds__(256) k_half_x(const float* __restrict__ x) {
    size_t idx = (size_t)blockIdx.x * 256 + threadIdx.x;
    if (idx >= (size_t)NR * DD / 4) return;
    size_t e = idx * 4;
    int d4 = (int)(e & 127);
    int r = (int)(e >> 7);
    int t = r >> 7, b = r & 127;
    float4 v = *reinterpret_cast<const float4*>(x + ((size_t)b * TT + t) * DD + d4);
    __half2* dst = reinterpret_cast<__half2*>(g_xh) + idx * 2;
    dst[0] = __floats2half2_rn(v.x, v.y);
    dst[1] = __floats2half2_rn(v.z, v.w);
}

__global__ void __launch_bounds__(256) k_prep_wk(const float* __restrict__ Wk) {
    size_t idx = (size_t)blockIdx.x * 256 + threadIdx.x;
    if (idx >= (size_t)K1NP * K1K) return;
    int i = (int)(idx % K1K);
    int n = (int)(idx / K1K);
    float w = (n < GG) ? Wk[(size_t)i * GG + n] : 0.f;
    g_wkh[idx] = __float2half(w);
}

__global__ void __launch_bounds__(256) k_prep_wr(const float* __restrict__ Wr) {
    size_t idx = (size_t)blockIdx.x * 256 + threadIdx.x;
    if (idx >= (size_t)K2NP * HH) return;
    int k = (int)(idx % HH);
    int n = (int)(idx / HH);
    float w = (n < GG) ? Wr[(size_t)k * GG + n] : 0.f;
    g_wrh[idx] = __float2half(w);
}

__global__ void __launch_bounds__(256) k_prep_w(const float* __restrict__ Wc) {
    size_t idx = (size_t)blockIdx.x * 256 + threadIdx.x;
    if (idx >= (size_t)NN * K3K) return;
    int i = (int)(idx % K3K);
    int n = (int)(idx / K3K);
    int k = n / HH, o = n - k * HH;
    g_wbh[idx] = __float2half(Wc[((size_t)o * HH + i) * CONVW + k]);
}

// ---------------- K1 GEMM (unchanged, proven) ----------------
#define ROWB 80
__global__ void __launch_bounds__(256, 2) k1_gemm(const float* __restrict__ Wk,
                                                  const float* __restrict__ bk) {
    __shared__ __align__(128) char sbuf[2][2 * 128 * ROWB];
    const int tid = threadIdx.x;
    const int wid = tid >> 5;
    const int lane = tid & 31;
    const int wm = wid >> 2, wn = wid & 3;
    const int n0 = blockIdx.x * 128;
    const size_t r0 = (size_t)blockIdx.y * 128;
    const int grow = tid >> 1, ghalf = tid & 1;
    uint32_t sA[2], sB[2];
#pragma unroll
    for (int s = 0; s < 2; ++s) {
        sA[s] = smem_u32(&sbuf[s][0]);
        sB[s] = smem_u32(&sbuf[s][128 * ROWB]);
    }
    const int q4 = lane >> 3;
    const uint32_t aoff = (uint32_t)(((q4 & 1) * 8 + (lane & 7)) * ROWB + (q4 >> 1) * 16);
    const uint32_t boff = (uint32_t)((lane & 7) * ROWB + ((lane >> 3) & 1) * 16);
    auto issue = [&](int ch) {
        const int kb = ch * 32;
        const int buf = ch & 1;
        const __half* ga = g_xh + (r0 + grow) * DD + kb + ghalf * 16;
        uint32_t da = sA[buf] + grow * ROWB + ghalf * 32;
        cp16(da, ga); cp16(da + 16, ga + 8);
        const __half* gb = g_wkh + (size_t)(n0 + grow) * K1K + kb + ghalf * 16;
        uint32_t db = sB[buf] + grow * ROWB + ghalf * 32;
        cp16(db, gb); cp16(db + 16, gb + 8);
        asm volatile("cp.async.commit_group;");
    };
    issue(0); issue(1);
    float c[4][4][4] = {};
    const int NCH1 = K1K / 32;
    for (int ch = 0; ch < NCH1; ++ch) {
        if (ch == NCH1 - 1) asm volatile("cp.async.wait_group 0;");
        else                asm volatile("cp.async.wait_group 1;");
        __syncthreads();
        const int buf = ch & 1;
        const uint32_t abase = sA[buf] + (wm * 64) * ROWB + aoff;
        const uint32_t bbase = sB[buf] + (wn * 32) * ROWB + boff;
#pragma unroll
        for (int s = 0; s < 2; ++s) {
            uint32_t a[4][4];
#pragma unroll
            for (int i = 0; i < 4; ++i) {
                asm volatile("ldmatrix.sync.aligned.m8n8.x4.shared.b16 {%0,%1,%2,%3}, [%4];"
                             : "=r"(a[i][0]), "=r"(a[i][1]), "=r"(a[i][2]), "=r"(a[i][3])
                             : "r"(abase + i * 16 * ROWB + s * 32));
            }
            uint32_t bf[4][2];
#pragma unroll
            for (int j = 0; j < 4; ++j) {
                asm volatile("ldmatrix.sync.aligned.m8n8.x2.shared.b16 {%0,%1}, [%2];"
                             : "=r"(bf[j][0]), "=r"(bf[j][1])
                             : "r"(bbase + j * 8 * ROWB + s * 32));
            }
#pragma unroll
            for (int i = 0; i < 4; ++i)
#pragma unroll
                for (int j = 0; j < 4; ++j)
                    asm volatile(
                        "mma.sync.aligned.m16n8k16.row.col.f32.f16.f16.f32 "
                        "{%0,%1,%2,%3}, {%4,%5,%6,%7}, {%8,%9}, {%0,%1,%2,%3};"
                        : "+f"(c[i][j][0]), "+f"(c[i][j][1]), "+f"(c[i][j][2]), "+f"(c[i][j][3])
                        : "r"(a[i][0]), "r"(a[i][1]), "r"(a[i][2]), "r"(a[i][3]),
                          "r"(bf[j][0]), "r"(bf[j][1]));
        }
        __syncthreads();
        if (ch + 2 < NCH1) issue(ch + 2);
    }
    const int gq = lane >> 2, t4 = lane & 3;
#pragma unroll
    for (int i = 0; i < 4; ++i) {
        size_t row = r0 + wm * 64 + i * 16 + gq;
#pragma unroll
        for (int j = 0; j < 4; ++j) {
            int g = n0 + wn * 32 + j * 8 + t4 * 2;
            if (g < GG) {
                float b0v = Wk[(size_t)DD * GG + g] + bk[g];
                float b1v = Wk[(size_t)DD * GG + g + 1] + bk[g + 1];
                g_xk[row * GG + g]           = c[i][j][0] + b0v;
                g_xk[row * GG + g + 1]       = c[i][j][1] + b1v;
                g_xk[(row + 8) * GG + g]     = c[i][j][2] + b0v;
                g_xk[(row + 8) * GG + g + 1] = c[i][j][3] + b1v;
            }
        }
    }
}

// ---------------- K2: persistent fp16 HMMA scan, 4 independent groups ----------------
// 100 blocks = 4 groups (32 batch rows) x 25 n-tiles (64 cols of GG).
// Group-local barriers; masters/ew group-local; cell state in registers.
#define K2_PAD 784
#define K2_SM_W 0
#define K2_SM_A 50176
#define K2_SM_MST 75264
#define K2_SM_BIAS 75776
#define K2_SMEM 76288

__global__ void __launch_bounds__(256) k2_recurrent(const float* __restrict__ Wr,
                                                    const float* __restrict__ br) {
    extern __shared__ __align__(16) char s2[];
    const int tid = threadIdx.x;
    const int bid = blockIdx.x;
    const int mt = bid / 25, nt = bid % 25;
    const int bm0 = mt * 32;
    const int n0 = nt * 64;

    // persistent W (fp16): 64 rows x 48 16B-chunks
    for (int q = tid; q < 64 * 48; q += 256) {
        int row = q / 48, cc = q % 48;
        *reinterpret_cast<uint4*>(s2 + K2_SM_W + row * K2_PAD + cc * 16) =
            *reinterpret_cast<const uint4*>(g_wrh + (size_t)(n0 + row) * HH + cc * 8);
    }
    float* s_bias = reinterpret_cast<float*>(s2 + K2_SM_BIAS);
    for (int n = tid; n < 64; n += 256) {
        int g = n0 + n;
        s_bias[n] = (g < GG) ? (Wr[(size_t)HH * GG + g] + br[g]) : 0.f;
    }
    float* s_mst = reinterpret_cast<float*>(s2 + K2_SM_MST);
    __syncthreads();

    unsigned seq = g_r2[mt][0];   // monotonic base (replay-safe)

    const int wid = tid >> 5, lane = tid & 31;
    const int wr = wid >> 2, wc = wid & 3;
    const int q4 = lane >> 3;
    const uint32_t fo = (uint32_t)(((q4 & 1) * 8 + (lane & 7)) * K2_PAD + (q4 >> 1) * 16);
    const uint32_t sbase = smem_u32(s2);
    const uint32_t a_base = sbase + K2_SM_A + wr * 16 * K2_PAD + fo;
    const uint32_t b_base = sbase + K2_SM_W + wc * 16 * K2_PAD + fo;
    const int gq = lane >> 2, t4 = lane & 3;

    // ew ownership: blocks nt=0..23 each own 512 elems of the group's 32x384
    const int e0 = nt * 512 + tid;
    const int e1 = e0 + 256;
    float creg0 = 0.f, creg1 = 0.f;

    for (int t = 0; t < TT; ++t) {
        float acc[2][4] = {};
        if (t > 0) {
            const size_t rb = (size_t)(t - 1) * BB + bm0;
            for (int q = tid; q < 32 * 48; q += 256) {
                int row = q / 48, cc = q % 48;
                uint4 v = __ldcg(reinterpret_cast<const uint4*>(
                    g_hf + (rb + row) * HH + cc * 8));
                *reinterpret_cast<uint4*>(s2 + K2_SM_A + row * K2_PAD + cc * 16) = v;
            }
            __syncthreads();
#pragma unroll
            for (int ki = 0; ki < 24; ++ki) {
                uint32_t a[4], b[4];
                asm volatile("ldmatrix.sync.aligned.m8n8.x4.shared.b16 {%0,%1,%2,%3}, [%4];"
                             : "=r"(a[0]), "=r"(a[1]), "=r"(a[2]), "=r"(a[3])
                             : "r"(a_base + ki * 32));
                asm volatile("ldmatrix.sync.aligned.m8n8.x4.shared.b16 {%0,%1,%2,%3}, [%4];"
                             : "=r"(b[0]), "=r"(b[1]), "=r"(b[2]), "=r"(b[3])
                             : "r"(b_base + ki * 32));
                asm volatile(
                    "mma.sync.aligned.m16n8k16.row.col.f32.f16.f16.f32 "
                    "{%0,%1,%2,%3}, {%4,%5,%6,%7}, {%8,%9}, {%0,%1,%2,%3};"
                    : "+f"(acc[0][0]), "+f"(acc[0][1]), "+f"(acc[0][2]), "+f"(acc[0][3])
                    : "r"(a[0]), "r"(a[1]), "r"(a[2]), "r"(a[3]),
                      "r"(b[0]), "r"(b[2]));
                asm volatile(
                    "mma.sync.aligned.m16n8k16.row.col.f32.f16.f16.f32 "
                    "{%0,%1,%2,%3}, {%4,%5,%6,%7}, {%8,%9}, {%0,%1,%2,%3};"
                    : "+f"(acc[1][0]), "+f"(acc[1][1]), "+f"(acc[1][2]), "+f"(acc[1][3])
                    : "r"(a[0]), "r"(a[1]), "r"(a[2]), "r"(a[3]),
                      "r"(b[1]), "r"(b[3]));
            }
        }
        // epilogue -> g_xout (group rows, this block's 64 cols) + xk
        {
            const float* xkrow = g_xk + (size_t)t * BB * GG;
            int b1 = bm0 + wr * 16 + gq;
            int b2 = b1 + 8;
#pragma unroll
            for (int j = 0; j < 2; ++j) {
                int col = wc * 16 + j * 8 + t4 * 2;
                int g = n0 + col;
                if (g < GG) {
                    float bi0 = s_bias[col], bi1 = s_bias[col + 1];
                    g_xout[b1 * GG + g]     = acc[j][0] + bi0 + __ldcg(&xkrow[(size_t)b1 * GG + g]);
                    g_xout[b1 * GG + g + 1] = acc[j][1] + bi1 + __ldcg(&xkrow[(size_t)b1 * GG + g + 1]);
                    g_xout[b2 * GG + g]     = acc[j][2] + bi0 + __ldcg(&xkrow[(size_t)b2 * GG + g]);
                    g_xout[b2 * GG + g + 1] = acc[j][3] + bi1 + __ldcg(&xkrow[(size_t)b2 * GG + g + 1]);
                }
            }
        }
        ++seq; k2bar(mt, nt, seq);

        // masters: this group's 32 rows only
        if (tid < 32) {
            int b = bm0 + tid;
            const float* row = g_xout + b * GG;
            float m0 = __ldcg(&row[0]), m1 = __ldcg(&row[1]), m2 = __ldcg(&row[2]);
            float v0 = __ldcg(&row[3]), v1 = __ldcg(&row[4]), v2 = __ldcg(&row[5]);
            float mx = fmaxf(m0, fmaxf(m1, m2));
            float e0f = expf(m0 - mx), e1f = expf(m1 - mx), e2f = expf(m2 - mx);
            float inv = 1.f / (e0f + e1f + e2f);
            float f0 = e0f * inv, f1 = (e0f + e1f) * inv;
            mx = fmaxf(v0, fmaxf(v1, v2));
            e0f = expf(v0 - mx); e1f = expf(v1 - mx); e2f = expf(v2 - mx);
            inv = 1.f / (e0f + e1f + e2f);
            s_mst[tid * 4 + 0] = f0;
            s_mst[tid * 4 + 1] = f1;
            s_mst[tid * 4 + 2] = (e1f + e2f) * inv;
            s_mst[tid * 4 + 3] = e2f * inv;
            if (nt == 0) g_dist[t * BB + b] = 1.f - (f0 + f1 + 1.f) * (1.f / 3.f);
        }
        __syncthreads();

        // elementwise: blocks 0..23 own fixed 512-elem slices; c in registers
        if (nt < 24) {
            __half* hft = g_hf + (size_t)t * BB * HH;
            auto do_e = [&](int e, float& cr) {
                int bl = e / 384, i = e - bl * 384;
                int l = i >> 7, c127 = i & 127;
                int b = bm0 + bl;
                float fm = (l == 0) ? s_mst[bl * 4] : ((l == 1) ? s_mst[bl * 4 + 1] : 1.f);
                float im = (l == 0) ? 1.f : ((l == 1) ? s_mst[bl * 4 + 2] : s_mst[bl * 4 + 3]);
                float ov = fm * im;
                const float* row = g_xout + b * GG;
                float gf = __ldcg(&row[6 + l * 128 + c127]);
                float gi = __ldcg(&row[6 + (3 + l) * 128 + c127]);
                float go = __ldcg(&row[6 + (6 + l) * 128 + c127]);
                float gc = __ldcg(&row[6 + (9 + l) * 128 + c127]);
                float fg = 1.f / (1.f + expf(-gf));
                float ig = 1.f / (1.f + expf(-gi));
                float og = 1.f / (1.f + expf(-go));
                float ci = tanhf(gc);
                float cn = (ov * fg + fm - ov) * cr + (ov * ig + im - ov) * ci;
                float hn = og * tanhf(cn);
                cr = cn;
                hft[(size_t)b * HH + i] = __float2half(hn);
            };
            do_e(e0, creg0);
            do_e(e1, creg1);
        }
        ++seq; k2bar(mt, nt, seq);
    }
}

// ---------------- K_dis ----------------
__global__ void k_dis() {
    int idx = blockIdx.x * 256 + threadIdx.x;
    if (idx >= NR) return;
    int t = idx >> 7, b = idx & 127;
    float c[CONVW];
    float cum = 0.f;
#pragma unroll
    for (int k = 0; k < CONVW; ++k) {
        int s = t - (CONVW - 1) + k;
        float d = (s >= 0) ? g_dist[s * BB + b] : 0.f;
        cum += d;
        c[k] = cum;
    }
    float mx = c[0];
#pragma unroll
    for (int k = 1; k < CONVW; ++k) mx = fmaxf(mx, c[k]);
    float sum = 0.f;
#pragma unroll
    for (int k = 0; k < CONVW; ++k) { c[k] = expf(c[k] - mx); sum += c[k]; }
    float inv = 1.f / sum;
#pragma unroll
    for (int k = 0; k < CONVW; ++k) g_dis[(size_t)idx * CONVW + k] = c[k] * inv;
}

// ---------------- K3 GEMM (unchanged, proven) ----------------
#define KSTEP 32
#define NCH3 (K3K / KSTEP)
__global__ void __launch_bounds__(256, 2) k3_gemm() {
    __shared__ __align__(128) char sbuf[2][2 * 128 * ROWB];
    const int tid = threadIdx.x;
    const int wid = tid >> 5;
    const int lane = tid & 31;
    const int wm = wid >> 2, wn = wid & 3;
    const int n0 = blockIdx.x * 128;
    const size_t r0 = (size_t)blockIdx.y * 128;
    const int grow = tid >> 1, ghalf = tid & 1;
    uint32_t sA[2], sB[2];
#pragma unroll
    for (int s = 0; s < 2; ++s) {
        sA[s] = smem_u32(&sbuf[s][0]);
        sB[s] = smem_u32(&sbuf[s][128 * ROWB]);
    }
    const int q4 = lane >> 3;
    const uint32_t aoff = (uint32_t)(((q4 & 1) * 8 + (lane & 7)) * ROWB + (q4 >> 1) * 16);
    const uint32_t boff = (uint32_t)((lane & 7) * ROWB + ((lane >> 3) & 1) * 16);
    auto issue = [&](int ch) {
        const int kb = ch * KSTEP;
        const int buf = ch & 1;
        const __half* ga = g_hf + (r0 + grow) * HH + kb + ghalf * 16;
        uint32_t da = sA[buf] + grow * ROWB + ghalf * 32;
        cp16(da, ga); cp16(da + 16, ga + 8);
        const __half* gb = g_wbh + (size_t)(n0 + grow) * K3K + kb + ghalf * 16;
        uint32_t db = sB[buf] + grow * ROWB + ghalf * 32;
        cp16(db, gb); cp16(db + 16, gb + 8);
        asm volatile("cp.async.commit_group;");
    };
    issue(0); issue(1);
    float c[4][4][4] = {};
    for (int ch = 0; ch < NCH3; ++ch) {
        if (ch == NCH3 - 1) asm volatile("cp.async.wait_group 0;");
        else                asm volatile("cp.async.wait_group 1;");
        __syncthreads();
        const int buf = ch & 1;
        const uint32_t abase = sA[buf] + (wm * 64) * ROWB + aoff;
        const uint32_t bbase = sB[buf] + (wn * 32) * ROWB + boff;
#pragma unroll
        for (int s = 0; s < 2; ++s) {
            uint32_t a[4][4];
#pragma unroll
            for (int i = 0; i < 4; ++i) {
                asm volatile("ldmatrix.sync.aligned.m8n8.x4.shared.b16 {%0,%1,%2,%3}, [%4];"
                             : "=r"(a[i][0]), "=r"(a[i][1]), "=r"(a[i][2]), "=r"(a[i][3])
                             : "r"(abase + i * 16 * ROWB + s * 32));
            }
            uint32_t bfr[4][2];
#pragma unroll
            for (int j = 0; j < 4; ++j) {
                asm volatile("ldmatrix.sync.aligned.m8n8.x2.shared.b16 {%0,%1}, [%2];"
                             : "=r"(bfr[j][0]), "=r"(bfr[j][1])
                             : "r"(bbase + j * 8 * ROWB + s * 32));
            }
#pragma unroll
            for (int i = 0; i < 4; ++i)
#pragma unroll
                for (int j = 0; j < 4; ++j)
                    asm volatile(
                        "mma.sync.aligned.m16n8k16.row.col.f32.f16.f16.f32 "
                        "{%0,%1,%2,%3}, {%4,%5,%6,%7}, {%8,%9}, {%0,%1,%2,%3};"
                        : "+f"(c[i][j][0]), "+f"(c[i][j][1]), "+f"(c[i][j][2]), "+f"(c[i][j][3])
                        : "r"(a[i][0]), "r"(a[i][1]), "r"(a[i][2]), "r"(a[i][3]),
                          "r"(bfr[j][0]), "r"(bfr[j][1]));
        }
        __syncthreads();
        if (ch + 2 < NCH3) issue(ch + 2);
    }
    const int gq = lane >> 2, t4 = lane & 3;
#pragma unroll
    for (int i = 0; i < 4; ++i) {
        size_t row = r0 + wm * 64 + i * 16 + gq;
        float* dst0 = g_A + row * NN + n0 + wn * 32 + t4 * 2;
        float* dst1 = g_A + (row + 8) * NN + n0 + wn * 32 + t4 * 2;
#pragma unroll
        for (int j = 0; j < 4; ++j) {
            *reinterpret_cast<float2*>(dst0 + j * 8) = make_float2(c[i][j][0], c[i][j][1]);
            *reinterpret_cast<float2*>(dst1 + j * 8) = make_float2(c[i][j][2], c[i][j][3]);
        }
    }
}

// ---------------- K4: gather + theme MLP + output (fp16 h) ----------------
__global__ void __launch_bounds__(256) k4_out(const float* __restrict__ Ws,
                                              const float* __restrict__ bs,
                                              const float* __restrict__ Wrs,
                                              const float* __restrict__ brs,
                                              const float* __restrict__ bc,
                                              float* __restrict__ out) {
    __shared__ float s_mh[16][HH];
    __shared__ float s_q[16][HSS];
    __shared__ float s_dis2[16][10];
    const int tid = threadIdx.x;
    const int r0 = blockIdx.x * 16;
    const int t = r0 >> 7, b0 = r0 & 127;
    for (int lin = tid; lin < 160; lin += 256) {
        int rr = lin / 10, k = lin % 10;
        s_dis2[rr][k] = g_dis[(size_t)(r0 + rr) * CONVW + k];
    }
    __syncthreads();
    for (int idx = tid; idx < 16 * HH; idx += 256) {
        int rr = idx / HH, i = idx - rr * HH;
        float acc = 0.f;
#pragma unroll
        for (int k = 0; k < CONVW; ++k) {
            int s = t - (CONVW - 1) + k;
            if (s >= 0)
                acc += s_dis2[rr][k] *
                       __half2float(g_hf[((size_t)s * BB + b0 + rr) * HH + i]);
        }
        s_mh[rr][i] = acc * (1.f / CONVW);
    }
    __syncthreads();
    for (int idx = tid; idx < 16 * HSS; idx += 256) {
        int rr = idx >> 6, j = idx & 63;
        float acc = bs[j];
        for (int i = 0; i < HH; ++i) acc += s_mh[rr][i] * Ws[i * HSS + j];
        s_q[rr][j] = fmaxf(acc, 0.f);
    }
    __syncthreads();
    for (int idx = tid; idx < 16 * HH; idx += 256) {
        int rr = idx / HH, o = idx - rr * HH;
        float acc = brs[o];
#pragma unroll 8
        for (int j = 0; j < HSS; ++j) acc += s_q[rr][j] * Wrs[j * HH + o];
        float theme = 1.f / (1.f + expf(-acc));
        int b = b0 + rr;
        float conv = bc[o];
#pragma unroll
        for (int k = 0; k < CONVW; ++k) {
            int s = t - (CONVW - 1) + k;
            if (s >= 0)
                conv += s_dis2[rr][k] * g_A[((size_t)s * BB + b) * NN + (size_t)k * HH + o];
        }
        out[((size_t)b * TT + t) * HH + o] =
            theme * conv + __half2float(g_hf[((size_t)t * BB + b) * HH + o]);
    }
}

// ---------------- entry ----------------
extern "C" void kernel_launch(void* const* d_in, const int* in_sizes, int n_in,
                              void* d_out, int out_size) {
    (void)in_sizes; (void)n_in; (void)out_size;
    const float* x   = (const float*)d_in[0];
    const float* Wk  = (const float*)d_in[2];
    const float* bk  = (const float*)d_in[3];
    const float* Wr  = (const float*)d_in[4];
    const float* br  = (const float*)d_in[5];
    const float* Ws  = (const float*)d_in[6];
    const float* bs  = (const float*)d_in[7];
    const float* Wrs = (const float*)d_in[8];
    const float* brs = (const float*)d_in[9];
    const float* Wc  = (const float*)d_in[10];
    const float* bc  = (const float*)d_in[11];
    float* out = (float*)d_out;

    cudaFuncSetAttribute(k2_recurrent, cudaFuncAttributeMaxDynamicSharedMemorySize, K2_SMEM);

    k_prep_w<<<(int)(((size_t)NN * K3K + 255) / 256), 256>>>(Wc);
    k_prep_wk<<<(int)(((size_t)K1NP * K1K + 255) / 256), 256>>>(Wk);
    k_prep_wr<<<(int)(((size_t)K2NP * HH + 255) / 256), 256>>>(Wr);
    k_half_x<<<(int)(((size_t)NR * DD / 4 + 255) / 256), 256>>>(x);
    k1_gemm<<<dim3(13, 512), 256>>>(Wk, bk);
    k2_recurrent<<<100, 256, K2_SMEM>>>(Wr, br);
    k_dis<<<(NR + 255) / 256, 256>>>();
    k3_gemm<<<dim3(30, 512), 256>>>();
    k4_out<<<4096, 256>>>(Ws, bs, Wrs, brs, bc, out);
}